// round 14
// baseline (speedup 1.0000x reference)
#include <cuda_runtime.h>
#include <cuda_fp16.h>
#include <math.h>
#include <stdint.h>

// ---------------------------------------------------------------------------
// Problem constants
// ---------------------------------------------------------------------------
#define B_   4
#define T_   2048
#define D_   1024
#define H_   16
#define G_   4
#define HD_  64
#define BT_  (B_ * T_)          // 8192
#define QKVW 1536                // fused Q|K|V projection width
#define SC_LOG2E 0.18033688011112042f   // 0.125 * log2(e)

// ---------------------------------------------------------------------------
// Scratch (device globals -- no allocation allowed)
// ---------------------------------------------------------------------------
__device__ float2 g_cs[T_ * 32];

__device__ __half g_qkv16[BT_ * QKVW];    // fused q|k|v projection (fp16)
__device__ __half g_x16[BT_ * D_];
__device__ __half g_wqkv16[QKVW * D_];    // Wq | Wk | Wv rows
__device__ __half g_wo16[D_ * D_];
__device__ __half g_q16[BT_ * D_];        // pre-scaled by 0.125*log2e
__device__ __half g_k16[BT_ * G_ * HD_];
__device__ __half g_vt16[B_ * G_ * HD_ * T_];
__device__ __half g_o16[BT_ * D_];

// ---------------------------------------------------------------------------
// PTX helpers (base sm_100-legal)
// ---------------------------------------------------------------------------
__device__ __forceinline__ uint32_t smem_u32(const void* p) {
    uint32_t a;
    asm("{ .reg .u64 t; cvta.to.shared.u64 t, %1; cvt.u32.u64 %0, t; }"
        : "=r"(a) : "l"(p));
    return a;
}
__device__ __forceinline__ void ldsm_x4(uint32_t (&r)[4], uint32_t addr) {
    asm volatile("ldmatrix.sync.aligned.m8n8.x4.shared.b16 {%0,%1,%2,%3}, [%4];"
                 : "=r"(r[0]), "=r"(r[1]), "=r"(r[2]), "=r"(r[3]) : "r"(addr));
}
__device__ __forceinline__ void mma_f16(float (&d)[4], const uint32_t (&a)[4],
                                        uint32_t b0, uint32_t b1) {
    asm volatile(
        "mma.sync.aligned.m16n8k16.row.col.f32.f16.f16.f32 "
        "{%0,%1,%2,%3}, {%4,%5,%6,%7}, {%8,%9}, {%0,%1,%2,%3};"
        : "+f"(d[0]), "+f"(d[1]), "+f"(d[2]), "+f"(d[3])
        : "r"(a[0]), "r"(a[1]), "r"(a[2]), "r"(a[3]), "r"(b0), "r"(b1));
}
__device__ __forceinline__ float ex2(float x) {
    float y;
    asm("ex2.approx.ftz.f32 %0, %1;" : "=f"(y) : "f"(x));
    return y;
}
__device__ __forceinline__ uint32_t pack_h2(float x, float y) {
    __half2 h = __floats2half2_rn(x, y);
    return *(uint32_t*)&h;
}
#define STS128(addr, v) \
    asm volatile("st.shared.v4.b32 [%0], {%1,%2,%3,%4};" \
                 :: "r"(addr), "r"((v).x), "r"((v).y), "r"((v).z), "r"((v).w))
#define CP_ASYNC16(dst, src) \
    asm volatile("cp.async.cg.shared.global [%0], [%1], 16;" \
                 :: "r"(dst), "l"(src))
#define CP_COMMIT() asm volatile("cp.async.commit_group;" ::: "memory")
#define CP_WAIT1()  asm volatile("cp.async.wait_group 1;" ::: "memory")
#define CP_WAIT0()  asm volatile("cp.async.wait_group 0;" ::: "memory")

// ---------------------------------------------------------------------------
// Fused prologue: x->fp16, Wq|Wk|Wv|Wo->fp16, rope table. One launch.
// ---------------------------------------------------------------------------
#define NB_X   8192
#define NB_WQ  1024
#define NB_WK  256
#define NB_WV  256
#define NB_WO  1024
#define NB_CS  256
#define NB_TOT (NB_X + NB_WQ + NB_WK + NB_WV + NB_WO + NB_CS)

__global__ void __launch_bounds__(256)
prep(const float* __restrict__ x,  const float* __restrict__ Wq,
     const float* __restrict__ Wk, const float* __restrict__ Wv,
     const float* __restrict__ Wo,
     __half* __restrict__ x16, __half* __restrict__ wqkv16,
     __half* __restrict__ wo16, float2* __restrict__ cs)
{
    const int bid = blockIdx.x;
    const int tid = threadIdx.x;

    const float* src; __half* dst; int i;
    if (bid < NB_X) {
        i = bid * 256 + tid; src = x; dst = x16;
    } else if (bid < NB_X + NB_WQ) {
        i = (bid - NB_X) * 256 + tid; src = Wq; dst = wqkv16;
    } else if (bid < NB_X + NB_WQ + NB_WK) {
        i = (bid - NB_X - NB_WQ) * 256 + tid;
        src = Wk; dst = wqkv16 + (size_t)D_ * D_;
    } else if (bid < NB_X + NB_WQ + NB_WK + NB_WV) {
        i = (bid - NB_X - NB_WQ - NB_WK) * 256 + tid;
        src = Wv; dst = wqkv16 + (size_t)(D_ + 256) * D_;
    } else if (bid < NB_X + NB_WQ + NB_WK + NB_WV + NB_WO) {
        i = (bid - NB_X - NB_WQ - NB_WK - NB_WV) * 256 + tid;
        src = Wo; dst = wo16;
    } else {
        const int idx = (bid - (NB_TOT - NB_CS)) * 256 + tid;
        const int t = idx >> 5, l = idx & 31;
        double inv_freq = pow(10000.0, -(double)l / 32.0);
        double ang = (double)t * inv_freq;
        cs[idx] = make_float2((float)cos(ang), (float)sin(ang));
        return;
    }
    float4 v = ((const float4*)src)[i];
    uint2 o = {pack_h2(v.x, v.y), pack_h2(v.z, v.w)};
    ((uint2*)dst)[i] = o;
}

// ---------------------------------------------------------------------------
// Tensor-core GEMM (HMMA fp16): C[M,N] = A16[M,K] @ B16[N,K]^T.
// CTA 128x128, 8 warps, warp tile 64x32, KC=32, 3-stage cp.async, 2 CTAs/SM.
// ---------------------------------------------------------------------------
#define KC      32
#define LDT     40
#define ATILEB  (128 * LDT * 2)
#define BTILEB  (128 * LDT * 2)
#define STAGEB  (ATILEB + BTILEB)
#define GEMM_SMEM (3 * STAGEB)            // 61440 B

template <bool HOUT>
__global__ void __launch_bounds__(256, 2)
gemm_h1(const __half* __restrict__ A16, const __half* __restrict__ B16,
        void* __restrict__ Cv, int M, int N, int K)
{
    extern __shared__ char smraw[];
    const uint32_t sb = smem_u32(smraw);

    const int tid  = threadIdx.x;
    const int lane = tid & 31;
    const int wid  = tid >> 5;
    const int wm   = wid & 1;
    const int wn   = wid >> 1;
    const int m0 = blockIdx.y * 128;
    const int n0 = blockIdx.x * 128;

    const int r0   = tid >> 2;
    const int cseg = (tid & 3) * 8;
    const __half* pA = A16 + (size_t)(m0 + r0) * K + cseg;
    const __half* pB = B16 + (size_t)(n0 + r0) * K + cseg;
    const uint32_t dA = (uint32_t)(r0 * LDT + cseg) * 2;
    const size_t rstep = (size_t)64 * K;
    const uint32_t dstep = 64 * LDT * 2;

    const uint32_t a_off = (uint32_t)(((wm * 64 + (lane & 15)) * LDT
                                       + (lane >> 4) * 8) * 2);
    const uint32_t b4_off = (uint32_t)(((wn * 32 + (lane & 7)
                                         + ((lane >> 4) & 1) * 8) * LDT) * 2
                                       + ((lane >> 3) & 1) * 16);

    float acc[4][4][4];
#pragma unroll
    for (int i = 0; i < 4; i++)
#pragma unroll
        for (int j = 0; j < 4; j++)
#pragma unroll
            for (int e = 0; e < 4; e++) acc[i][j][e] = 0.f;

    const int nch = K / KC;

#define ISSUE(c) do {                                                       \
        const uint32_t st_ = sb + ((c) % 3) * STAGEB;                       \
        const size_t k0_ = (size_t)(c) * KC;                                \
        CP_ASYNC16(st_ + dA,                    pA + k0_);                  \
        CP_ASYNC16(st_ + dA + dstep,            pA + k0_ + rstep);          \
        CP_ASYNC16(st_ + ATILEB + dA,           pB + k0_);                  \
        CP_ASYNC16(st_ + ATILEB + dA + dstep,   pB + k0_ + rstep);          \
        CP_COMMIT();                                                        \
    } while (0)

    ISSUE(0);
    ISSUE(1);

    for (int c = 0; c < nch; c++) {
        if (c + 2 < nch) CP_WAIT1(); else CP_WAIT0();
        __syncthreads();
        if (c + 2 < nch) ISSUE(c + 2);

        const uint32_t tb = sb + (c % 3) * STAGEB;
        const uint32_t aT = tb;
        const uint32_t bT = tb + ATILEB;

#pragma unroll
        for (int ks = 0; ks < 2; ks++) {
            const uint32_t ksb = ks * 32;
            uint32_t af[4][4];
#pragma unroll
            for (int mt = 0; mt < 4; mt++)
                ldsm_x4(af[mt], aT + a_off + mt * (16 * LDT * 2) + ksb);
#pragma unroll
            for (int ntp = 0; ntp < 2; ntp++) {
                uint32_t bh[4];
                ldsm_x4(bh, bT + b4_off + ntp * (16 * LDT * 2) + ksb);
#pragma unroll
                for (int mt = 0; mt < 4; mt++) {
                    mma_f16(acc[mt][2 * ntp],     af[mt], bh[0], bh[1]);
                    mma_f16(acc[mt][2 * ntp + 1], af[mt], bh[2], bh[3]);
                }
            }
        }
    }
#undef ISSUE

#pragma unroll
    for (int mt = 0; mt < 4; mt++) {
        const int r = m0 + wm * 64 + mt * 16 + (lane >> 2);
#pragma unroll
        for (int nt = 0; nt < 4; nt++) {
            const int cc = n0 + wn * 32 + nt * 8 + (lane & 3) * 2;
            if (HOUT) {
                __half* C = (__half*)Cv;
                *(uint32_t*)&C[(size_t)r * N + cc] =
                    pack_h2(acc[mt][nt][0], acc[mt][nt][1]);
                *(uint32_t*)&C[(size_t)(r + 8) * N + cc] =
                    pack_h2(acc[mt][nt][2], acc[mt][nt][3]);
            } else {
                float* C = (float*)Cv;
                float2 v0 = {acc[mt][nt][0], acc[mt][nt][1]};
                float2 v1 = {acc[mt][nt][2], acc[mt][nt][3]};
                *(float2*)&C[(size_t)r * N + cc]       = v0;
                *(float2*)&C[(size_t)(r + 8) * N + cc] = v1;
            }
        }
    }
}

// ---------------------------------------------------------------------------
// Fused pointwise: RMSNorm+RoPE for q (pre-scaled by 0.125*log2e) and k,
// plus V transpose. One launch, block-range split.
// ---------------------------------------------------------------------------
#define NB_RQ (BT_ * H_ / 8)   // 16384
#define NB_RK (BT_ * G_ / 8)   // 4096
#define NB_V  (T_ / 64 * G_ * B_)  // 512

__global__ void __launch_bounds__(256)
postproc(const __half* __restrict__ qkv,
         const float* __restrict__ qn_w, const float* __restrict__ kn_w,
         __half* __restrict__ q16, __half* __restrict__ k16,
         __half* __restrict__ vt16, const float2* __restrict__ cs)
{
    __shared__ __half sv[64][72];
    const int tid = threadIdx.x;

    if (blockIdx.x >= NB_RQ + NB_RK) {
        // ---- V transpose branch ----
        const int vb = blockIdx.x - NB_RQ - NB_RK;
        const int t0 = (vb & 31) * 64;
        const int g  = (vb >> 5) & 3;
        const int b  = vb >> 7;
        const __half* v = qkv + D_ + 256 + g * HD_;
#pragma unroll
        for (int it = 0; it < 2; it++) {
            int tr = it * 32 + (tid >> 3);
            int c8 = (tid & 7) * 8;
            uint4 raw = *(const uint4*)&v[(size_t)(b * T_ + t0 + tr) * QKVW + c8];
            *(uint4*)&sv[tr][c8] = raw;
        }
        __syncthreads();
        const int hd  = tid >> 2;
        const int seg = tid & 3;
        __half hv[16];
#pragma unroll
        for (int j = 0; j < 16; j++)
            hv[j] = sv[seg * 16 + j][hd];
        const size_t ob = ((size_t)(b * G_ + g) * HD_ + hd) * T_ + t0 + seg * 16;
        *(uint4*)&vt16[ob]     = *(uint4*)&hv[0];
        *(uint4*)&vt16[ob + 8] = *(uint4*)&hv[8];
        return;
    }

    // ---- RMSNorm + RoPE branches ----
    const int lane   = tid & 31;
    const int warpid = tid >> 5;

    const __half* p;
    const float* w;
    __half* outp;
    int t;
    bool isq;
    if (blockIdx.x < NB_RQ) {
        const int row  = blockIdx.x * 8 + warpid;
        const int bt   = row >> 4;
        const int head = row & 15;
        t = bt & (T_ - 1);
        p = qkv + (size_t)bt * QKVW + head * HD_;
        w = qn_w;
        outp = q16 + (size_t)bt * D_ + head * HD_;
        isq = true;
    } else {
        const int row = (blockIdx.x - NB_RQ) * 8 + warpid;
        const int bt  = row >> 2;
        const int g   = row & 3;
        t = bt & (T_ - 1);
        p = qkv + (size_t)bt * QKVW + D_ + g * HD_;
        w = kn_w;
        outp = k16 + (size_t)bt * (G_ * HD_) + g * HD_;
        isq = false;
    }

    __half2 xh = *(const __half2*)&p[2 * lane];
    float x0 = __half2float(__low2half(xh));
    float x1 = __half2float(__high2half(xh));

    float ss = x0 * x0 + x1 * x1;
#pragma unroll
    for (int o = 16; o > 0; o >>= 1)
        ss += __shfl_xor_sync(0xffffffffu, ss, o);

    float rms = rsqrtf(ss * (1.0f / HD_) + 1e-6f);
    float xn1 = x0 * rms * w[2 * lane];
    float xn2 = x1 * rms * w[2 * lane + 1];

    float2 csv = cs[t * 32 + lane];
    float ox = xn1 * csv.x - xn2 * csv.y;
    float oy = xn2 * csv.x + xn1 * csv.y;
    if (isq) { ox *= SC_LOG2E; oy *= SC_LOG2E; }

    *(uint32_t*)&outp[2 * lane] = pack_h2(ox, oy);
}

// ---------------------------------------------------------------------------
// Causal GQA flash attention, HMMA fp16, fixed-base softmax (no running max).
// Q pre-scaled by 0.125*log2e -> p = ex2(s) directly.
// CTA = 128 q-rows, 4 warps (32 rows each), 64-key tiles,
// cp.async double-buffered K/V, 2 CTAs/SM.
// ---------------------------------------------------------------------------
#define ASTR  72
#define ATILE (64 * ASTR * 2)            // 9216 B
#define AQT   (128 * ASTR * 2)           // 18432 B
#define KVSTG (2 * ATILE)                // 18432 B per stage (K, V)
#define ATT_SMEM (AQT + 2 * KVSTG)       // 55296 B

__global__ void __launch_bounds__(128)
attn_mma(const __half* __restrict__ q16, const __half* __restrict__ k16,
         const __half* __restrict__ vt16, __half* __restrict__ o16)
{
    extern __shared__ char smraw[];
    const uint32_t sb  = smem_u32(smraw);
    const uint32_t sQ  = sb;
    const uint32_t sKV = sb + AQT;

    const int tid  = threadIdx.x;
    const int lane = tid & 31;
    const int w    = tid >> 5;
    const int mblk = gridDim.x - 1 - blockIdx.x;
    const int m0   = mblk * 128;
    const int h    = blockIdx.y;
    const int b    = blockIdx.z;
    const int g    = h >> 2;

    const __half* khb = k16 + ((size_t)b * T_ * G_ + g) * HD_;
    const __half* vhb = vt16 + (size_t)(b * G_ + g) * HD_ * T_;

    const int ntiles = (m0 + 128) / 64;

    const int ar = tid >> 3;             // 0..15
    const int ac = (tid & 7) * 8;
#define AISSUE(n0_, stg_) do {                                               \
        const uint32_t st_ = sKV + (uint32_t)(stg_) * KVSTG;                 \
        _Pragma("unroll")                                                    \
        for (int it_ = 0; it_ < 4; it_++) {                                  \
            const int rr_ = it_ * 16 + ar;                                   \
            const uint32_t so_ = (uint32_t)(rr_ * ASTR + ac) * 2;            \
            CP_ASYNC16(st_ + so_,         khb + (size_t)((n0_) + rr_) * (G_ * HD_) + ac); \
            CP_ASYNC16(st_ + ATILE + so_, vhb + (size_t)rr_ * T_ + (n0_) + ac); \
        }                                                                    \
        CP_COMMIT();                                                         \
    } while (0)

    AISSUE(0, 0);

    {
        const __half* qp = q16 + ((size_t)(b * T_ + m0) * H_ + h) * HD_;
        const uint32_t soff = (uint32_t)(ar * ASTR + ac) * 2;
#pragma unroll
        for (int it = 0; it < 8; it++) {
            uint4 a = *(const uint4*)(qp + (size_t)(it * 16 + ar) * (H_ * HD_) + ac);
            STS128(sQ + it * 16 * ASTR * 2 + soff, a);
        }
    }
    __syncthreads();

    uint32_t qf[2][4][4];
#pragma unroll
    for (int mt = 0; mt < 2; mt++) {
        const uint32_t a_off = (uint32_t)((w * 32 + mt * 16 + (lane & 15)) * ASTR * 2
                                          + (lane >> 4) * 16);
#pragma unroll
        for (int ks = 0; ks < 4; ks++)
            ldsm_x4(qf[mt][ks], sQ + a_off + ks * 32);
    }

    float o[2][8][4];
#pragma unroll
    for (int mt = 0; mt < 2; mt++)
#pragma unroll
        for (int nt = 0; nt < 8; nt++)
#pragma unroll
            for (int e = 0; e < 4; e++) o[mt][nt][e] = 0.f;
    float lrow[2][2] = {{0.f, 0.f}, {0.f, 0.f}};   // per-thread partial sums

    const uint32_t b4_off = (uint32_t)((((lane & 7) + ((lane >> 4) & 1) * 8) * ASTR) * 2
                                       + ((lane >> 3) & 1) * 16);

    for (int t = 0; t < ntiles; t++) {
        CP_WAIT0();
        __syncthreads();
        if (t + 1 < ntiles) AISSUE((t + 1) * 64, (t + 1) & 1);

        const int n0 = t * 64;
        const uint32_t kvb = sKV + (uint32_t)(t & 1) * KVSTG;
        const uint32_t sK  = kvb;
        const uint32_t sV  = kvb + ATILE;

        const bool skip = (n0 > m0 + w * 32 + 31);
        if (!skip) {
            const bool needm = (n0 + 63 > m0 + w * 32);

            // ---- S = Qs K^T (S already includes 0.125*log2e) ----
            float s[2][8][4];
#pragma unroll
            for (int mt = 0; mt < 2; mt++)
#pragma unroll
                for (int nt = 0; nt < 8; nt++)
#pragma unroll
                    for (int e = 0; e < 4; e++) s[mt][nt][e] = 0.f;

#pragma unroll
            for (int ks = 0; ks < 4; ks++) {
#pragma unroll
                for (int ntp = 0; ntp < 4; ntp++) {
                    const uint32_t bo = b4_off + ntp * (16 * ASTR * 2) + ks * 32;
                    uint32_t bh[4];
                    ldsm_x4(bh, sK + bo);
#pragma unroll
                    for (int mt = 0; mt < 2; mt++) {
                        mma_f16(s[mt][2 * ntp],     qf[mt][ks], bh[0], bh[1]);
                        mma_f16(s[mt][2 * ntp + 1], qf[mt][ks], bh[2], bh[3]);
                    }
                }
            }

            // ---- fixed-base softmax: p = 2^s, masked -> 0 ----
            uint32_t ap[2][4][4];
#pragma unroll
            for (int mt = 0; mt < 2; mt++) {
                const int grow0 = m0 + w * 32 + mt * 16 + (lane >> 2);
                const int grow1 = grow0 + 8;
                float s0 = 0.f, s1 = 0.f;
#pragma unroll
                for (int nt = 0; nt < 8; nt++) {
                    const int col = n0 + nt * 8 + (lane & 3) * 2;
                    float p0 = ex2(s[mt][nt][0]);
                    float p1 = ex2(s[mt][nt][1]);
                    float p2 = ex2(s[mt][nt][2]);
                    float p3 = ex2(s[mt][nt][3]);
                    if (needm) {
                        if (col     > grow0) p0 = 0.f;
                        if (col + 1 > grow0) p1 = 0.f;
                        if (col     > grow1) p2 = 0.f;
                        if (col + 1 > grow1) p3 = 0.f;
                    }
                    s0 += p0 + p1; s1 += p2 + p3;
                    s[mt][nt][0] = p0; s[mt][nt][1] = p1;
                    s[mt][nt][2] = p2; s[mt][nt][3] = p3;
                }
                lrow[mt][0] += s0;
                lrow[mt][1] += s1;
#pragma unroll
                for (int ks = 0; ks < 4; ks++) {
                    ap[mt][ks][0] = pack_h2(s[mt][2 * ks][0],     s[mt][2 * ks][1]);
                    ap[mt][ks][1] = pack_h2(s[mt][2 * ks][2],     s[mt][2 * ks][3]);
                    ap[mt][ks][2] = pack_h2(s[mt][2 * ks + 1][0], s[mt][2 * ks + 1][1]);
                    ap[mt][ks][3] = pack_h2(s[mt][2 * ks + 1][2], s[mt][2 * ks + 1][3]);
                }
            }

            // ---- O += P16 V16 (no rescaling needed) ----
#pragma unroll
            for (int ntp = 0; ntp < 4; ntp++) {
#pragma unroll
                for (int ks = 0; ks < 4; ks++) {
                    const uint32_t bo = b4_off + ntp * (16 * ASTR * 2) + ks * 32;
                    uint32_t vh[4];
                    ldsm_x4(vh, sV + bo);
#pragma unroll
                    for (int mt = 0; mt < 2; mt++) {
                        mma_f16(o[mt][2 * ntp],     ap[mt][ks], vh[0], vh[1]);
                        mma_f16(o[mt][2 * ntp + 1], ap[mt][ks], vh[2], vh[3]);
                    }
                }
            }
        }
    }
#undef AISSUE

    // ---- epilogue: quad-reduce l, normalize, emit fp16 ----
#pragma unroll
    for (int mt = 0; mt < 2; mt++) {
        float l0 = lrow[mt][0];
        float l1 = lrow[mt][1];
        l0 += __shfl_xor_sync(0xffffffffu, l0, 1);
        l0 += __shfl_xor_sync(0xffffffffu, l0, 2);
        l1 += __shfl_xor_sync(0xffffffffu, l1, 1);
        l1 += __shfl_xor_sync(0xffffffffu, l1, 2);
        const float i0 = 1.f / l0;
        const float i1 = 1.f / l1;
        const int grow = m0 + w * 32 + mt * 16 + (lane >> 2);
        const size_t base0 = (size_t)(b * T_ + grow) * D_ + h * HD_ + (lane & 3) * 2;
        const size_t base1 = base0 + 8 * D_;
#pragma unroll
        for (int nt = 0; nt < 8; nt++) {
            *(uint32_t*)&o16[base0 + nt * 8] =
                pack_h2(o[mt][nt][0] * i0, o[mt][nt][1] * i0);
            *(uint32_t*)&o16[base1 + nt * 8] =
                pack_h2(o[mt][nt][2] * i1, o[mt][nt][3] * i1);
        }
    }
}

// ---------------------------------------------------------------------------
// Launch
// ---------------------------------------------------------------------------
extern "C" void kernel_launch(void* const* d_in, const int* in_sizes, int n_in,
                              void* d_out, int out_size)
{
    const float* x    = (const float*)d_in[0];
    const float* Wq   = (const float*)d_in[1];
    const float* Wk   = (const float*)d_in[2];
    const float* Wv   = (const float*)d_in[3];
    const float* Wo   = (const float*)d_in[4];
    const float* qn_w = (const float*)d_in[5];
    const float* kn_w = (const float*)d_in[6];
    float* out = (float*)d_out;

    float2* cs;
    __half *qkv16, *x16, *wqkv16, *wo16, *q16, *k16, *vt16, *o16;
    cudaGetSymbolAddress((void**)&cs, g_cs);
    cudaGetSymbolAddress((void**)&qkv16, g_qkv16);
    cudaGetSymbolAddress((void**)&x16, g_x16);
    cudaGetSymbolAddress((void**)&wqkv16, g_wqkv16);
    cudaGetSymbolAddress((void**)&wo16, g_wo16);
    cudaGetSymbolAddress((void**)&q16, g_q16);
    cudaGetSymbolAddress((void**)&k16, g_k16);
    cudaGetSymbolAddress((void**)&vt16, g_vt16);
    cudaGetSymbolAddress((void**)&o16, g_o16);

    cudaFuncSetAttribute(gemm_h1<true>,
                         cudaFuncAttributeMaxDynamicSharedMemorySize, GEMM_SMEM);
    cudaFuncSetAttribute(gemm_h1<false>,
                         cudaFuncAttributeMaxDynamicSharedMemorySize, GEMM_SMEM);
    cudaFuncSetAttribute(attn_mma,
                         cudaFuncAttributeMaxDynamicSharedMemorySize, ATT_SMEM);

    // --- fused prologue ---
    prep<<<NB_TOT, 256>>>(x, Wq, Wk, Wv, Wo, x16, wqkv16, wo16, cs);

    // --- fused QKV projection (fp16 output) ---
    gemm_h1<true><<<dim3(QKVW / 128, BT_ / 128), 256, GEMM_SMEM>>>(
        x16, wqkv16, qkv16, BT_, QKVW, D_);

    // --- fused pointwise: RMSNorm+RoPE (q,k) + V transpose ---
    postproc<<<NB_RQ + NB_RK + NB_V, 256>>>(qkv16, qn_w, kn_w,
                                            q16, k16, vt16, cs);

    // --- causal GQA flash attention (fixed-base softmax) ---
    attn_mma<<<dim3(T_ / 128, H_, B_), 128, ATT_SMEM>>>(q16, k16, vt16, o16);

    // --- output projection (fp32 output) ---
    gemm_h1<false><<<dim3(D_ / 128, BT_ / 128), 256, GEMM_SMEM>>>(
        o16, wo16, out, BT_, D_, D_);
}

// round 15
// speedup vs baseline: 1.0355x; 1.0355x over previous
#include <cuda_runtime.h>
#include <cuda_fp16.h>
#include <math.h>
#include <stdint.h>

// ---------------------------------------------------------------------------
// Problem constants
// ---------------------------------------------------------------------------
#define B_   4
#define T_   2048
#define D_   1024
#define H_   16
#define G_   4
#define HD_  64
#define BT_  (B_ * T_)          // 8192
#define QKVW 1536                // fused Q|K|V projection width
#define SC_LOG2E 0.18033688011112042f   // 0.125 * log2(e)

// ---------------------------------------------------------------------------
// Scratch (device globals -- no allocation allowed)
// ---------------------------------------------------------------------------
__device__ float2 g_cs[T_ * 32];

__device__ __half g_qkv16[BT_ * QKVW];    // fused q|k|v projection (fp16)
__device__ __half g_x16[BT_ * D_];
__device__ __half g_wqkv16[QKVW * D_];    // Wq | Wk | Wv rows
__device__ __half g_wo16[D_ * D_];
__device__ __half g_q16[BT_ * D_];        // pre-scaled by 0.125*log2e
__device__ __half g_k16[BT_ * G_ * HD_];
__device__ __half g_vt16[B_ * G_ * HD_ * T_];
__device__ __half g_o16[BT_ * D_];

// ---------------------------------------------------------------------------
// PTX helpers (base sm_100-legal)
// ---------------------------------------------------------------------------
__device__ __forceinline__ uint32_t smem_u32(const void* p) {
    uint32_t a;
    asm("{ .reg .u64 t; cvta.to.shared.u64 t, %1; cvt.u32.u64 %0, t; }"
        : "=r"(a) : "l"(p));
    return a;
}
__device__ __forceinline__ void ldsm_x4(uint32_t (&r)[4], uint32_t addr) {
    asm volatile("ldmatrix.sync.aligned.m8n8.x4.shared.b16 {%0,%1,%2,%3}, [%4];"
                 : "=r"(r[0]), "=r"(r[1]), "=r"(r[2]), "=r"(r[3]) : "r"(addr));
}
__device__ __forceinline__ void mma_f16(float (&d)[4], const uint32_t (&a)[4],
                                        uint32_t b0, uint32_t b1) {
    asm volatile(
        "mma.sync.aligned.m16n8k16.row.col.f32.f16.f16.f32 "
        "{%0,%1,%2,%3}, {%4,%5,%6,%7}, {%8,%9}, {%0,%1,%2,%3};"
        : "+f"(d[0]), "+f"(d[1]), "+f"(d[2]), "+f"(d[3])
        : "r"(a[0]), "r"(a[1]), "r"(a[2]), "r"(a[3]), "r"(b0), "r"(b1));
}
__device__ __forceinline__ float ex2(float x) {
    float y;
    asm("ex2.approx.ftz.f32 %0, %1;" : "=f"(y) : "f"(x));
    return y;
}
__device__ __forceinline__ uint32_t pack_h2(float x, float y) {
    __half2 h = __floats2half2_rn(x, y);
    return *(uint32_t*)&h;
}
#define STS128(addr, v) \
    asm volatile("st.shared.v4.b32 [%0], {%1,%2,%3,%4};" \
                 :: "r"(addr), "r"((v).x), "r"((v).y), "r"((v).z), "r"((v).w))
#define CP_ASYNC16(dst, src) \
    asm volatile("cp.async.cg.shared.global [%0], [%1], 16;" \
                 :: "r"(dst), "l"(src))
#define CP_COMMIT() asm volatile("cp.async.commit_group;" ::: "memory")
#define CP_WAIT1()  asm volatile("cp.async.wait_group 1;" ::: "memory")
#define CP_WAIT0()  asm volatile("cp.async.wait_group 0;" ::: "memory")

// ---------------------------------------------------------------------------
// Fused prologue: x->fp16, Wq|Wk|Wv|Wo->fp16, rope table. One launch.
// ---------------------------------------------------------------------------
#define NB_X   8192
#define NB_WQ  1024
#define NB_WK  256
#define NB_WV  256
#define NB_WO  1024
#define NB_CS  256
#define NB_TOT (NB_X + NB_WQ + NB_WK + NB_WV + NB_WO + NB_CS)

__global__ void __launch_bounds__(256)
prep(const float* __restrict__ x,  const float* __restrict__ Wq,
     const float* __restrict__ Wk, const float* __restrict__ Wv,
     const float* __restrict__ Wo,
     __half* __restrict__ x16, __half* __restrict__ wqkv16,
     __half* __restrict__ wo16, float2* __restrict__ cs)
{
    const int bid = blockIdx.x;
    const int tid = threadIdx.x;

    const float* src; __half* dst; int i;
    if (bid < NB_X) {
        i = bid * 256 + tid; src = x; dst = x16;
    } else if (bid < NB_X + NB_WQ) {
        i = (bid - NB_X) * 256 + tid; src = Wq; dst = wqkv16;
    } else if (bid < NB_X + NB_WQ + NB_WK) {
        i = (bid - NB_X - NB_WQ) * 256 + tid;
        src = Wk; dst = wqkv16 + (size_t)D_ * D_;
    } else if (bid < NB_X + NB_WQ + NB_WK + NB_WV) {
        i = (bid - NB_X - NB_WQ - NB_WK) * 256 + tid;
        src = Wv; dst = wqkv16 + (size_t)(D_ + 256) * D_;
    } else if (bid < NB_X + NB_WQ + NB_WK + NB_WV + NB_WO) {
        i = (bid - NB_X - NB_WQ - NB_WK - NB_WV) * 256 + tid;
        src = Wo; dst = wo16;
    } else {
        const int idx = (bid - (NB_TOT - NB_CS)) * 256 + tid;
        const int t = idx >> 5, l = idx & 31;
        double inv_freq = pow(10000.0, -(double)l / 32.0);
        double ang = (double)t * inv_freq;
        cs[idx] = make_float2((float)cos(ang), (float)sin(ang));
        return;
    }
    float4 v = ((const float4*)src)[i];
    uint2 o = {pack_h2(v.x, v.y), pack_h2(v.z, v.w)};
    ((uint2*)dst)[i] = o;
}

// ---------------------------------------------------------------------------
// Tensor-core GEMM (HMMA fp16): C[M,N] = A16[M,K] @ B16[N,K]^T.
// CTA 128x128, 8 warps, warp tile 64x32, KC=32, 3-stage cp.async, 2 CTAs/SM.
// ---------------------------------------------------------------------------
#define KC      32
#define LDT     40
#define ATILEB  (128 * LDT * 2)
#define BTILEB  (128 * LDT * 2)
#define STAGEB  (ATILEB + BTILEB)
#define GEMM_SMEM (3 * STAGEB)            // 61440 B

template <bool HOUT>
__global__ void __launch_bounds__(256, 2)
gemm_h1(const __half* __restrict__ A16, const __half* __restrict__ B16,
        void* __restrict__ Cv, int M, int N, int K)
{
    extern __shared__ char smraw[];
    const uint32_t sb = smem_u32(smraw);

    const int tid  = threadIdx.x;
    const int lane = tid & 31;
    const int wid  = tid >> 5;
    const int wm   = wid & 1;
    const int wn   = wid >> 1;
    const int m0 = blockIdx.y * 128;
    const int n0 = blockIdx.x * 128;

    const int r0   = tid >> 2;
    const int cseg = (tid & 3) * 8;
    const __half* pA = A16 + (size_t)(m0 + r0) * K + cseg;
    const __half* pB = B16 + (size_t)(n0 + r0) * K + cseg;
    const uint32_t dA = (uint32_t)(r0 * LDT + cseg) * 2;
    const size_t rstep = (size_t)64 * K;
    const uint32_t dstep = 64 * LDT * 2;

    const uint32_t a_off = (uint32_t)(((wm * 64 + (lane & 15)) * LDT
                                       + (lane >> 4) * 8) * 2);
    const uint32_t b4_off = (uint32_t)(((wn * 32 + (lane & 7)
                                         + ((lane >> 4) & 1) * 8) * LDT) * 2
                                       + ((lane >> 3) & 1) * 16);

    float acc[4][4][4];
#pragma unroll
    for (int i = 0; i < 4; i++)
#pragma unroll
        for (int j = 0; j < 4; j++)
#pragma unroll
            for (int e = 0; e < 4; e++) acc[i][j][e] = 0.f;

    const int nch = K / KC;

#define ISSUE(c) do {                                                       \
        const uint32_t st_ = sb + ((c) % 3) * STAGEB;                       \
        const size_t k0_ = (size_t)(c) * KC;                                \
        CP_ASYNC16(st_ + dA,                    pA + k0_);                  \
        CP_ASYNC16(st_ + dA + dstep,            pA + k0_ + rstep);          \
        CP_ASYNC16(st_ + ATILEB + dA,           pB + k0_);                  \
        CP_ASYNC16(st_ + ATILEB + dA + dstep,   pB + k0_ + rstep);          \
        CP_COMMIT();                                                        \
    } while (0)

    ISSUE(0);
    ISSUE(1);

    for (int c = 0; c < nch; c++) {
        if (c + 2 < nch) CP_WAIT1(); else CP_WAIT0();
        __syncthreads();
        if (c + 2 < nch) ISSUE(c + 2);

        const uint32_t tb = sb + (c % 3) * STAGEB;
        const uint32_t aT = tb;
        const uint32_t bT = tb + ATILEB;

#pragma unroll
        for (int ks = 0; ks < 2; ks++) {
            const uint32_t ksb = ks * 32;
            uint32_t af[4][4];
#pragma unroll
            for (int mt = 0; mt < 4; mt++)
                ldsm_x4(af[mt], aT + a_off + mt * (16 * LDT * 2) + ksb);
#pragma unroll
            for (int ntp = 0; ntp < 2; ntp++) {
                uint32_t bh[4];
                ldsm_x4(bh, bT + b4_off + ntp * (16 * LDT * 2) + ksb);
#pragma unroll
                for (int mt = 0; mt < 4; mt++) {
                    mma_f16(acc[mt][2 * ntp],     af[mt], bh[0], bh[1]);
                    mma_f16(acc[mt][2 * ntp + 1], af[mt], bh[2], bh[3]);
                }
            }
        }
    }
#undef ISSUE

#pragma unroll
    for (int mt = 0; mt < 4; mt++) {
        const int r = m0 + wm * 64 + mt * 16 + (lane >> 2);
#pragma unroll
        for (int nt = 0; nt < 4; nt++) {
            const int cc = n0 + wn * 32 + nt * 8 + (lane & 3) * 2;
            if (HOUT) {
                __half* C = (__half*)Cv;
                *(uint32_t*)&C[(size_t)r * N + cc] =
                    pack_h2(acc[mt][nt][0], acc[mt][nt][1]);
                *(uint32_t*)&C[(size_t)(r + 8) * N + cc] =
                    pack_h2(acc[mt][nt][2], acc[mt][nt][3]);
            } else {
                float* C = (float*)Cv;
                float2 v0 = {acc[mt][nt][0], acc[mt][nt][1]};
                float2 v1 = {acc[mt][nt][2], acc[mt][nt][3]};
                *(float2*)&C[(size_t)r * N + cc]       = v0;
                *(float2*)&C[(size_t)(r + 8) * N + cc] = v1;
            }
        }
    }
}

// ---------------------------------------------------------------------------
// Fused pointwise: RMSNorm+RoPE for q (pre-scaled) and k, plus V transpose.
// ---------------------------------------------------------------------------
#define NB_RQ (BT_ * H_ / 8)   // 16384
#define NB_RK (BT_ * G_ / 8)   // 4096
#define NB_V  (T_ / 64 * G_ * B_)  // 512

__global__ void __launch_bounds__(256)
postproc(const __half* __restrict__ qkv,
         const float* __restrict__ qn_w, const float* __restrict__ kn_w,
         __half* __restrict__ q16, __half* __restrict__ k16,
         __half* __restrict__ vt16, const float2* __restrict__ cs)
{
    __shared__ __half sv[64][72];
    const int tid = threadIdx.x;

    if (blockIdx.x >= NB_RQ + NB_RK) {
        const int vb = blockIdx.x - NB_RQ - NB_RK;
        const int t0 = (vb & 31) * 64;
        const int g  = (vb >> 5) & 3;
        const int b  = vb >> 7;
        const __half* v = qkv + D_ + 256 + g * HD_;
#pragma unroll
        for (int it = 0; it < 2; it++) {
            int tr = it * 32 + (tid >> 3);
            int c8 = (tid & 7) * 8;
            uint4 raw = *(const uint4*)&v[(size_t)(b * T_ + t0 + tr) * QKVW + c8];
            *(uint4*)&sv[tr][c8] = raw;
        }
        __syncthreads();
        const int hd  = tid >> 2;
        const int seg = tid & 3;
        __half hv[16];
#pragma unroll
        for (int j = 0; j < 16; j++)
            hv[j] = sv[seg * 16 + j][hd];
        const size_t ob = ((size_t)(b * G_ + g) * HD_ + hd) * T_ + t0 + seg * 16;
        *(uint4*)&vt16[ob]     = *(uint4*)&hv[0];
        *(uint4*)&vt16[ob + 8] = *(uint4*)&hv[8];
        return;
    }

    const int lane   = tid & 31;
    const int warpid = tid >> 5;

    const __half* p;
    const float* w;
    __half* outp;
    int t;
    bool isq;
    if (blockIdx.x < NB_RQ) {
        const int row  = blockIdx.x * 8 + warpid;
        const int bt   = row >> 4;
        const int head = row & 15;
        t = bt & (T_ - 1);
        p = qkv + (size_t)bt * QKVW + head * HD_;
        w = qn_w;
        outp = q16 + (size_t)bt * D_ + head * HD_;
        isq = true;
    } else {
        const int row = (blockIdx.x - NB_RQ) * 8 + warpid;
        const int bt  = row >> 2;
        const int g   = row & 3;
        t = bt & (T_ - 1);
        p = qkv + (size_t)bt * QKVW + D_ + g * HD_;
        w = kn_w;
        outp = k16 + (size_t)bt * (G_ * HD_) + g * HD_;
        isq = false;
    }

    __half2 xh = *(const __half2*)&p[2 * lane];
    float x0 = __half2float(__low2half(xh));
    float x1 = __half2float(__high2half(xh));

    float ss = x0 * x0 + x1 * x1;
#pragma unroll
    for (int o = 16; o > 0; o >>= 1)
        ss += __shfl_xor_sync(0xffffffffu, ss, o);

    float rms = rsqrtf(ss * (1.0f / HD_) + 1e-6f);
    float xn1 = x0 * rms * w[2 * lane];
    float xn2 = x1 * rms * w[2 * lane + 1];

    float2 csv = cs[t * 32 + lane];
    float ox = xn1 * csv.x - xn2 * csv.y;
    float oy = xn2 * csv.x + xn1 * csv.y;
    if (isq) { ox *= SC_LOG2E; oy *= SC_LOG2E; }

    *(uint32_t*)&outp[2 * lane] = pack_h2(ox, oy);
}

// ---------------------------------------------------------------------------
// Causal GQA flash attention, HMMA fp16, fixed-base softmax.
// CTA = 128 q-rows, 8 warps x 16 rows (256 threads), 64-key tiles,
// cp.async double-buffered K/V, 2 CTAs/SM -> 16 warps/SM.
// ---------------------------------------------------------------------------
#define ASTR  72
#define ATILE (64 * ASTR * 2)            // 9216 B
#define AQT   (128 * ASTR * 2)           // 18432 B
#define KVSTG (2 * ATILE)                // 18432 B per stage (K, V)
#define ATT_SMEM (AQT + 2 * KVSTG)       // 55296 B

__global__ void __launch_bounds__(256, 2)
attn_mma(const __half* __restrict__ q16, const __half* __restrict__ k16,
         const __half* __restrict__ vt16, __half* __restrict__ o16)
{
    extern __shared__ char smraw[];
    const uint32_t sb  = smem_u32(smraw);
    const uint32_t sQ  = sb;
    const uint32_t sKV = sb + AQT;

    const int tid  = threadIdx.x;
    const int lane = tid & 31;
    const int w    = tid >> 5;            // 0..7, rows [w*16, w*16+16)
    const int mblk = gridDim.x - 1 - blockIdx.x;
    const int m0   = mblk * 128;
    const int h    = blockIdx.y;
    const int b    = blockIdx.z;
    const int g    = h >> 2;

    const __half* khb = k16 + ((size_t)b * T_ * G_ + g) * HD_;
    const __half* vhb = vt16 + (size_t)(b * G_ + g) * HD_ * T_;

    const int ntiles = (m0 + 128) / 64;

    const int ar = tid >> 3;             // 0..31
    const int ac = (tid & 7) * 8;
#define AISSUE(n0_, stg_) do {                                               \
        const uint32_t st_ = sKV + (uint32_t)(stg_) * KVSTG;                 \
        _Pragma("unroll")                                                    \
        for (int it_ = 0; it_ < 2; it_++) {                                  \
            const int rr_ = it_ * 32 + ar;                                   \
            const uint32_t so_ = (uint32_t)(rr_ * ASTR + ac) * 2;            \
            CP_ASYNC16(st_ + so_,         khb + (size_t)((n0_) + rr_) * (G_ * HD_) + ac); \
            CP_ASYNC16(st_ + ATILE + so_, vhb + (size_t)rr_ * T_ + (n0_) + ac); \
        }                                                                    \
        CP_COMMIT();                                                         \
    } while (0)

    AISSUE(0, 0);

    // ---- stage Q tile (128 rows, 256 threads) ----
    {
        const __half* qp = q16 + ((size_t)(b * T_ + m0) * H_ + h) * HD_;
        const uint32_t soff = (uint32_t)(ar * ASTR + ac) * 2;
#pragma unroll
        for (int it = 0; it < 4; it++) {
            uint4 a = *(const uint4*)(qp + (size_t)(it * 32 + ar) * (H_ * HD_) + ac);
            STS128(sQ + it * 32 * ASTR * 2 + soff, a);
        }
    }
    __syncthreads();

    uint32_t qf[4][4];
    {
        const uint32_t a_off = (uint32_t)((w * 16 + (lane & 15)) * ASTR * 2
                                          + (lane >> 4) * 16);
#pragma unroll
        for (int ks = 0; ks < 4; ks++)
            ldsm_x4(qf[ks], sQ + a_off + ks * 32);
    }

    float o[8][4];
#pragma unroll
    for (int nt = 0; nt < 8; nt++)
#pragma unroll
        for (int e = 0; e < 4; e++) o[nt][e] = 0.f;
    float lrow0 = 0.f, lrow1 = 0.f;

    const uint32_t b4_off = (uint32_t)((((lane & 7) + ((lane >> 4) & 1) * 8) * ASTR) * 2
                                       + ((lane >> 3) & 1) * 16);

    for (int t = 0; t < ntiles; t++) {
        CP_WAIT0();
        __syncthreads();
        if (t + 1 < ntiles) AISSUE((t + 1) * 64, (t + 1) & 1);

        const int n0 = t * 64;
        const uint32_t kvb = sKV + (uint32_t)(t & 1) * KVSTG;
        const uint32_t sK  = kvb;
        const uint32_t sV  = kvb + ATILE;

        const bool skip = (n0 > m0 + w * 16 + 15);
        if (!skip) {
            const bool needm = (n0 + 63 > m0 + w * 16);

            // ---- S = Qs K^T ----
            float s[8][4];
#pragma unroll
            for (int nt = 0; nt < 8; nt++)
#pragma unroll
                for (int e = 0; e < 4; e++) s[nt][e] = 0.f;

#pragma unroll
            for (int ks = 0; ks < 4; ks++) {
#pragma unroll
                for (int ntp = 0; ntp < 4; ntp++) {
                    const uint32_t bo = b4_off + ntp * (16 * ASTR * 2) + ks * 32;
                    uint32_t bh[4];
                    ldsm_x4(bh, sK + bo);
                    mma_f16(s[2 * ntp],     qf[ks], bh[0], bh[1]);
                    mma_f16(s[2 * ntp + 1], qf[ks], bh[2], bh[3]);
                }
            }

            // ---- fixed-base softmax: p = 2^s, masked -> 0 ----
            uint32_t ap[4][4];
            {
                const int grow0 = m0 + w * 16 + (lane >> 2);
                const int grow1 = grow0 + 8;
                float s0 = 0.f, s1 = 0.f;
#pragma unroll
                for (int nt = 0; nt < 8; nt++) {
                    const int col = n0 + nt * 8 + (lane & 3) * 2;
                    float p0 = ex2(s[nt][0]);
                    float p1 = ex2(s[nt][1]);
                    float p2 = ex2(s[nt][2]);
                    float p3 = ex2(s[nt][3]);
                    if (needm) {
                        if (col     > grow0) p0 = 0.f;
                        if (col + 1 > grow0) p1 = 0.f;
                        if (col     > grow1) p2 = 0.f;
                        if (col + 1 > grow1) p3 = 0.f;
                    }
                    s0 += p0 + p1; s1 += p2 + p3;
                    s[nt][0] = p0; s[nt][1] = p1;
                    s[nt][2] = p2; s[nt][3] = p3;
                }
                lrow0 += s0;
                lrow1 += s1;
#pragma unroll
                for (int ks = 0; ks < 4; ks++) {
                    ap[ks][0] = pack_h2(s[2 * ks][0],     s[2 * ks][1]);
                    ap[ks][1] = pack_h2(s[2 * ks][2],     s[2 * ks][3]);
                    ap[ks][2] = pack_h2(s[2 * ks + 1][0], s[2 * ks + 1][1]);
                    ap[ks][3] = pack_h2(s[2 * ks + 1][2], s[2 * ks + 1][3]);
                }
            }

            // ---- O += P16 V16 ----
#pragma unroll
            for (int ntp = 0; ntp < 4; ntp++) {
#pragma unroll
                for (int ks = 0; ks < 4; ks++) {
                    const uint32_t bo = b4_off + ntp * (16 * ASTR * 2) + ks * 32;
                    uint32_t vh[4];
                    ldsm_x4(vh, sV + bo);
                    mma_f16(o[2 * ntp],     ap[ks], vh[0], vh[1]);
                    mma_f16(o[2 * ntp + 1], ap[ks], vh[2], vh[3]);
                }
            }
        }
    }
#undef AISSUE

    // ---- epilogue: quad-reduce l, normalize, emit fp16 ----
    {
        lrow0 += __shfl_xor_sync(0xffffffffu, lrow0, 1);
        lrow0 += __shfl_xor_sync(0xffffffffu, lrow0, 2);
        lrow1 += __shfl_xor_sync(0xffffffffu, lrow1, 1);
        lrow1 += __shfl_xor_sync(0xffffffffu, lrow1, 2);
        const float i0 = 1.f / lrow0;
        const float i1 = 1.f / lrow1;
        const int grow = m0 + w * 16 + (lane >> 2);
        const size_t base0 = (size_t)(b * T_ + grow) * D_ + h * HD_ + (lane & 3) * 2;
        const size_t base1 = base0 + 8 * D_;
#pragma unroll
        for (int nt = 0; nt < 8; nt++) {
            *(uint32_t*)&o16[base0 + nt * 8] =
                pack_h2(o[nt][0] * i0, o[nt][1] * i0);
            *(uint32_t*)&o16[base1 + nt * 8] =
                pack_h2(o[nt][2] * i1, o[nt][3] * i1);
        }
    }
}

// ---------------------------------------------------------------------------
// Launch
// ---------------------------------------------------------------------------
extern "C" void kernel_launch(void* const* d_in, const int* in_sizes, int n_in,
                              void* d_out, int out_size)
{
    const float* x    = (const float*)d_in[0];
    const float* Wq   = (const float*)d_in[1];
    const float* Wk   = (const float*)d_in[2];
    const float* Wv   = (const float*)d_in[3];
    const float* Wo   = (const float*)d_in[4];
    const float* qn_w = (const float*)d_in[5];
    const float* kn_w = (const float*)d_in[6];
    float* out = (float*)d_out;

    float2* cs;
    __half *qkv16, *x16, *wqkv16, *wo16, *q16, *k16, *vt16, *o16;
    cudaGetSymbolAddress((void**)&cs, g_cs);
    cudaGetSymbolAddress((void**)&qkv16, g_qkv16);
    cudaGetSymbolAddress((void**)&x16, g_x16);
    cudaGetSymbolAddress((void**)&wqkv16, g_wqkv16);
    cudaGetSymbolAddress((void**)&wo16, g_wo16);
    cudaGetSymbolAddress((void**)&q16, g_q16);
    cudaGetSymbolAddress((void**)&k16, g_k16);
    cudaGetSymbolAddress((void**)&vt16, g_vt16);
    cudaGetSymbolAddress((void**)&o16, g_o16);

    cudaFuncSetAttribute(gemm_h1<true>,
                         cudaFuncAttributeMaxDynamicSharedMemorySize, GEMM_SMEM);
    cudaFuncSetAttribute(gemm_h1<false>,
                         cudaFuncAttributeMaxDynamicSharedMemorySize, GEMM_SMEM);
    cudaFuncSetAttribute(attn_mma,
                         cudaFuncAttributeMaxDynamicSharedMemorySize, ATT_SMEM);

    // --- fused prologue ---
    prep<<<NB_TOT, 256>>>(x, Wq, Wk, Wv, Wo, x16, wqkv16, wo16, cs);

    // --- fused QKV projection (fp16 output) ---
    gemm_h1<true><<<dim3(QKVW / 128, BT_ / 128), 256, GEMM_SMEM>>>(
        x16, wqkv16, qkv16, BT_, QKVW, D_);

    // --- fused pointwise: RMSNorm+RoPE (q,k) + V transpose ---
    postproc<<<NB_RQ + NB_RK + NB_V, 256>>>(qkv16, qn_w, kn_w,
                                            q16, k16, vt16, cs);

    // --- causal GQA flash attention (8 warps x 16 rows, 2 CTAs/SM) ---
    attn_mma<<<dim3(T_ / 128, H_, B_), 256, ATT_SMEM>>>(q16, k16, vt16, o16);

    // --- output projection (fp32 output) ---
    gemm_h1<false><<<dim3(D_ / 128, BT_ / 128), 256, GEMM_SMEM>>>(
        o16, wo16, out, BT_, D_, D_);
}

// round 16
// speedup vs baseline: 1.0586x; 1.0223x over previous
#include <cuda_runtime.h>
#include <cuda_fp16.h>
#include <math.h>
#include <stdint.h>

// ---------------------------------------------------------------------------
// Problem constants
// ---------------------------------------------------------------------------
#define B_   4
#define T_   2048
#define D_   1024
#define H_   16
#define G_   4
#define HD_  64
#define BT_  (B_ * T_)          // 8192
#define QKVW 1536                // fused Q|K|V projection width
#define SC_LOG2E 0.18033688011112042f   // 0.125 * log2(e)

// ---------------------------------------------------------------------------
// Scratch (device globals -- no allocation allowed)
// ---------------------------------------------------------------------------
__device__ float2 g_cs[T_ * 32];

__device__ __half g_qkv16[BT_ * QKVW];    // fused q|k|v projection (fp16)
__device__ __half g_x16[BT_ * D_];
__device__ __half g_wqkv16[QKVW * D_];    // Wq | Wk | Wv rows
__device__ __half g_wo16[D_ * D_];
__device__ __half g_q16[BT_ * D_];        // pre-scaled by 0.125*log2e
__device__ __half g_k16[BT_ * G_ * HD_];
__device__ __half g_vt16[B_ * G_ * HD_ * T_];
__device__ __half g_o16[BT_ * D_];

// ---------------------------------------------------------------------------
// PTX helpers (base sm_100-legal)
// ---------------------------------------------------------------------------
__device__ __forceinline__ uint32_t smem_u32(const void* p) {
    uint32_t a;
    asm("{ .reg .u64 t; cvta.to.shared.u64 t, %1; cvt.u32.u64 %0, t; }"
        : "=r"(a) : "l"(p));
    return a;
}
__device__ __forceinline__ void ldsm_x4(uint32_t (&r)[4], uint32_t addr) {
    asm volatile("ldmatrix.sync.aligned.m8n8.x4.shared.b16 {%0,%1,%2,%3}, [%4];"
                 : "=r"(r[0]), "=r"(r[1]), "=r"(r[2]), "=r"(r[3]) : "r"(addr));
}
__device__ __forceinline__ void mma_f16(float (&d)[4], const uint32_t (&a)[4],
                                        uint32_t b0, uint32_t b1) {
    asm volatile(
        "mma.sync.aligned.m16n8k16.row.col.f32.f16.f16.f32 "
        "{%0,%1,%2,%3}, {%4,%5,%6,%7}, {%8,%9}, {%0,%1,%2,%3};"
        : "+f"(d[0]), "+f"(d[1]), "+f"(d[2]), "+f"(d[3])
        : "r"(a[0]), "r"(a[1]), "r"(a[2]), "r"(a[3]), "r"(b0), "r"(b1));
}
__device__ __forceinline__ float ex2(float x) {
    float y;
    asm("ex2.approx.ftz.f32 %0, %1;" : "=f"(y) : "f"(x));
    return y;
}
__device__ __forceinline__ uint32_t pack_h2(float x, float y) {
    __half2 h = __floats2half2_rn(x, y);
    return *(uint32_t*)&h;
}
#define STS128(addr, v) \
    asm volatile("st.shared.v4.b32 [%0], {%1,%2,%3,%4};" \
                 :: "r"(addr), "r"((v).x), "r"((v).y), "r"((v).z), "r"((v).w))
#define CP_ASYNC16(dst, src) \
    asm volatile("cp.async.cg.shared.global [%0], [%1], 16;" \
                 :: "r"(dst), "l"(src))
#define CP_COMMIT() asm volatile("cp.async.commit_group;" ::: "memory")
#define CP_WAIT1()  asm volatile("cp.async.wait_group 1;" ::: "memory")
#define CP_WAIT0()  asm volatile("cp.async.wait_group 0;" ::: "memory")

// ---------------------------------------------------------------------------
// Fused prologue: x->fp16, Wq|Wk|Wv|Wo->fp16, rope table. One launch.
// ---------------------------------------------------------------------------
#define NB_X   8192
#define NB_WQ  1024
#define NB_WK  256
#define NB_WV  256
#define NB_WO  1024
#define NB_CS  256
#define NB_TOT (NB_X + NB_WQ + NB_WK + NB_WV + NB_WO + NB_CS)

__global__ void __launch_bounds__(256)
prep(const float* __restrict__ x,  const float* __restrict__ Wq,
     const float* __restrict__ Wk, const float* __restrict__ Wv,
     const float* __restrict__ Wo,
     __half* __restrict__ x16, __half* __restrict__ wqkv16,
     __half* __restrict__ wo16, float2* __restrict__ cs)
{
    const int bid = blockIdx.x;
    const int tid = threadIdx.x;

    const float* src; __half* dst; int i;
    if (bid < NB_X) {
        i = bid * 256 + tid; src = x; dst = x16;
    } else if (bid < NB_X + NB_WQ) {
        i = (bid - NB_X) * 256 + tid; src = Wq; dst = wqkv16;
    } else if (bid < NB_X + NB_WQ + NB_WK) {
        i = (bid - NB_X - NB_WQ) * 256 + tid;
        src = Wk; dst = wqkv16 + (size_t)D_ * D_;
    } else if (bid < NB_X + NB_WQ + NB_WK + NB_WV) {
        i = (bid - NB_X - NB_WQ - NB_WK) * 256 + tid;
        src = Wv; dst = wqkv16 + (size_t)(D_ + 256) * D_;
    } else if (bid < NB_X + NB_WQ + NB_WK + NB_WV + NB_WO) {
        i = (bid - NB_X - NB_WQ - NB_WK - NB_WV) * 256 + tid;
        src = Wo; dst = wo16;
    } else {
        const int idx = (bid - (NB_TOT - NB_CS)) * 256 + tid;
        const int t = idx >> 5, l = idx & 31;
        double inv_freq = pow(10000.0, -(double)l / 32.0);
        double ang = (double)t * inv_freq;
        cs[idx] = make_float2((float)cos(ang), (float)sin(ang));
        return;
    }
    float4 v = ((const float4*)src)[i];
    uint2 o = {pack_h2(v.x, v.y), pack_h2(v.z, v.w)};
    ((uint2*)dst)[i] = o;
}

// ---------------------------------------------------------------------------
// Tensor-core GEMM (HMMA fp16): C[M,N] = A16[M,K] @ B16[N,K]^T.
// CTA 128x128, 8 warps, warp tile 64x32, KC=32, 3-stage cp.async, 2 CTAs/SM.
// ---------------------------------------------------------------------------
#define KC      32
#define LDT     40
#define ATILEB  (128 * LDT * 2)
#define BTILEB  (128 * LDT * 2)
#define STAGEB  (ATILEB + BTILEB)
#define GEMM_SMEM (3 * STAGEB)            // 61440 B

template <bool HOUT>
__global__ void __launch_bounds__(256, 2)
gemm_h1(const __half* __restrict__ A16, const __half* __restrict__ B16,
        void* __restrict__ Cv, int M, int N, int K)
{
    extern __shared__ char smraw[];
    const uint32_t sb = smem_u32(smraw);

    const int tid  = threadIdx.x;
    const int lane = tid & 31;
    const int wid  = tid >> 5;
    const int wm   = wid & 1;
    const int wn   = wid >> 1;
    const int m0 = blockIdx.y * 128;
    const int n0 = blockIdx.x * 128;

    const int r0   = tid >> 2;
    const int cseg = (tid & 3) * 8;
    const __half* pA = A16 + (size_t)(m0 + r0) * K + cseg;
    const __half* pB = B16 + (size_t)(n0 + r0) * K + cseg;
    const uint32_t dA = (uint32_t)(r0 * LDT + cseg) * 2;
    const size_t rstep = (size_t)64 * K;
    const uint32_t dstep = 64 * LDT * 2;

    const uint32_t a_off = (uint32_t)(((wm * 64 + (lane & 15)) * LDT
                                       + (lane >> 4) * 8) * 2);
    const uint32_t b4_off = (uint32_t)(((wn * 32 + (lane & 7)
                                         + ((lane >> 4) & 1) * 8) * LDT) * 2
                                       + ((lane >> 3) & 1) * 16);

    float acc[4][4][4];
#pragma unroll
    for (int i = 0; i < 4; i++)
#pragma unroll
        for (int j = 0; j < 4; j++)
#pragma unroll
            for (int e = 0; e < 4; e++) acc[i][j][e] = 0.f;

    const int nch = K / KC;

#define ISSUE(c) do {                                                       \
        const uint32_t st_ = sb + ((c) % 3) * STAGEB;                       \
        const size_t k0_ = (size_t)(c) * KC;                                \
        CP_ASYNC16(st_ + dA,                    pA + k0_);                  \
        CP_ASYNC16(st_ + dA + dstep,            pA + k0_ + rstep);          \
        CP_ASYNC16(st_ + ATILEB + dA,           pB + k0_);                  \
        CP_ASYNC16(st_ + ATILEB + dA + dstep,   pB + k0_ + rstep);          \
        CP_COMMIT();                                                        \
    } while (0)

    ISSUE(0);
    ISSUE(1);

    for (int c = 0; c < nch; c++) {
        if (c + 2 < nch) CP_WAIT1(); else CP_WAIT0();
        __syncthreads();
        if (c + 2 < nch) ISSUE(c + 2);

        const uint32_t tb = sb + (c % 3) * STAGEB;
        const uint32_t aT = tb;
        const uint32_t bT = tb + ATILEB;

#pragma unroll
        for (int ks = 0; ks < 2; ks++) {
            const uint32_t ksb = ks * 32;
            uint32_t af[4][4];
#pragma unroll
            for (int mt = 0; mt < 4; mt++)
                ldsm_x4(af[mt], aT + a_off + mt * (16 * LDT * 2) + ksb);
#pragma unroll
            for (int ntp = 0; ntp < 2; ntp++) {
                uint32_t bh[4];
                ldsm_x4(bh, bT + b4_off + ntp * (16 * LDT * 2) + ksb);
#pragma unroll
                for (int mt = 0; mt < 4; mt++) {
                    mma_f16(acc[mt][2 * ntp],     af[mt], bh[0], bh[1]);
                    mma_f16(acc[mt][2 * ntp + 1], af[mt], bh[2], bh[3]);
                }
            }
        }
    }
#undef ISSUE

#pragma unroll
    for (int mt = 0; mt < 4; mt++) {
        const int r = m0 + wm * 64 + mt * 16 + (lane >> 2);
#pragma unroll
        for (int nt = 0; nt < 4; nt++) {
            const int cc = n0 + wn * 32 + nt * 8 + (lane & 3) * 2;
            if (HOUT) {
                __half* C = (__half*)Cv;
                *(uint32_t*)&C[(size_t)r * N + cc] =
                    pack_h2(acc[mt][nt][0], acc[mt][nt][1]);
                *(uint32_t*)&C[(size_t)(r + 8) * N + cc] =
                    pack_h2(acc[mt][nt][2], acc[mt][nt][3]);
            } else {
                float* C = (float*)Cv;
                float2 v0 = {acc[mt][nt][0], acc[mt][nt][1]};
                float2 v1 = {acc[mt][nt][2], acc[mt][nt][3]};
                *(float2*)&C[(size_t)r * N + cc]       = v0;
                *(float2*)&C[(size_t)(r + 8) * N + cc] = v1;
            }
        }
    }
}

// ---------------------------------------------------------------------------
// Fused pointwise: RMSNorm+RoPE for q (pre-scaled) and k, plus V transpose.
// ---------------------------------------------------------------------------
#define NB_RQ (BT_ * H_ / 8)   // 16384
#define NB_RK (BT_ * G_ / 8)   // 4096
#define NB_V  (T_ / 64 * G_ * B_)  // 512

__global__ void __launch_bounds__(256)
postproc(const __half* __restrict__ qkv,
         const float* __restrict__ qn_w, const float* __restrict__ kn_w,
         __half* __restrict__ q16, __half* __restrict__ k16,
         __half* __restrict__ vt16, const float2* __restrict__ cs)
{
    __shared__ __half sv[64][72];
    const int tid = threadIdx.x;

    if (blockIdx.x >= NB_RQ + NB_RK) {
        const int vb = blockIdx.x - NB_RQ - NB_RK;
        const int t0 = (vb & 31) * 64;
        const int g  = (vb >> 5) & 3;
        const int b  = vb >> 7;
        const __half* v = qkv + D_ + 256 + g * HD_;
#pragma unroll
        for (int it = 0; it < 2; it++) {
            int tr = it * 32 + (tid >> 3);
            int c8 = (tid & 7) * 8;
            uint4 raw = *(const uint4*)&v[(size_t)(b * T_ + t0 + tr) * QKVW + c8];
            *(uint4*)&sv[tr][c8] = raw;
        }
        __syncthreads();
        const int hd  = tid >> 2;
        const int seg = tid & 3;
        __half hv[16];
#pragma unroll
        for (int j = 0; j < 16; j++)
            hv[j] = sv[seg * 16 + j][hd];
        const size_t ob = ((size_t)(b * G_ + g) * HD_ + hd) * T_ + t0 + seg * 16;
        *(uint4*)&vt16[ob]     = *(uint4*)&hv[0];
        *(uint4*)&vt16[ob + 8] = *(uint4*)&hv[8];
        return;
    }

    const int lane   = tid & 31;
    const int warpid = tid >> 5;

    const __half* p;
    const float* w;
    __half* outp;
    int t;
    bool isq;
    if (blockIdx.x < NB_RQ) {
        const int row  = blockIdx.x * 8 + warpid;
        const int bt   = row >> 4;
        const int head = row & 15;
        t = bt & (T_ - 1);
        p = qkv + (size_t)bt * QKVW + head * HD_;
        w = qn_w;
        outp = q16 + (size_t)bt * D_ + head * HD_;
        isq = true;
    } else {
        const int row = (blockIdx.x - NB_RQ) * 8 + warpid;
        const int bt  = row >> 2;
        const int g   = row & 3;
        t = bt & (T_ - 1);
        p = qkv + (size_t)bt * QKVW + D_ + g * HD_;
        w = kn_w;
        outp = k16 + (size_t)bt * (G_ * HD_) + g * HD_;
        isq = false;
    }

    __half2 xh = *(const __half2*)&p[2 * lane];
    float x0 = __half2float(__low2half(xh));
    float x1 = __half2float(__high2half(xh));

    float ss = x0 * x0 + x1 * x1;
#pragma unroll
    for (int o = 16; o > 0; o >>= 1)
        ss += __shfl_xor_sync(0xffffffffu, ss, o);

    float rms = rsqrtf(ss * (1.0f / HD_) + 1e-6f);
    float xn1 = x0 * rms * w[2 * lane];
    float xn2 = x1 * rms * w[2 * lane + 1];

    float2 csv = cs[t * 32 + lane];
    float ox = xn1 * csv.x - xn2 * csv.y;
    float oy = xn2 * csv.x + xn1 * csv.y;
    if (isq) { ox *= SC_LOG2E; oy *= SC_LOG2E; }

    *(uint32_t*)&outp[2 * lane] = pack_h2(ox, oy);
}

// ---------------------------------------------------------------------------
// Causal GQA flash attention, HMMA fp16, fixed-base softmax.
// CTA = 128 q-rows, 8 warps x 16 rows (256 threads), 2 CTAs/SM.
// 128-key smem stages (double-buffered), two 64-key compute halves per stage.
// K stage: 128 key-rows x ASTR. V stage: two 64-key subtiles (rows = hd).
// ---------------------------------------------------------------------------
#define ASTR  72
#define VSUB  (64 * ASTR * 2)            // 9216 B (64 hd-rows x 64 keys)
#define KSTG  (128 * ASTR * 2)           // 18432 B (128 key-rows)
#define KVSTG (KSTG + 2 * VSUB)          // 36864 B per stage
#define AQT   (128 * ASTR * 2)           // 18432 B
#define ATT_SMEM (AQT + 2 * KVSTG)       // 92160 B

__global__ void __launch_bounds__(256, 2)
attn_mma(const __half* __restrict__ q16, const __half* __restrict__ k16,
         const __half* __restrict__ vt16, __half* __restrict__ o16)
{
    extern __shared__ char smraw[];
    const uint32_t sb  = smem_u32(smraw);
    const uint32_t sQ  = sb;
    const uint32_t sKV = sb + AQT;

    const int tid  = threadIdx.x;
    const int lane = tid & 31;
    const int w    = tid >> 5;            // 0..7, rows [w*16, w*16+16)
    const int mblk = gridDim.x - 1 - blockIdx.x;
    const int m0   = mblk * 128;
    const int h    = blockIdx.y;
    const int b    = blockIdx.z;
    const int g    = h >> 2;

    const __half* khb = k16 + ((size_t)b * T_ * G_ + g) * HD_;
    const __half* vhb = vt16 + (size_t)(b * G_ + g) * HD_ * T_;

    const int ntiles = mblk + 1;          // 128-key tiles

    const int ar = tid >> 3;             // 0..31
    const int ac = (tid & 7) * 8;
    // K: 128 key-rows x 64 hd ; V: 64 hd-rows x 128 keys -> 2 subtiles
#define AISSUE(n0_, stg_) do {                                               \
        const uint32_t st_ = sKV + (uint32_t)(stg_) * KVSTG;                 \
        _Pragma("unroll")                                                    \
        for (int it_ = 0; it_ < 4; it_++) {                                  \
            const int rr_ = it_ * 32 + ar;                                   \
            CP_ASYNC16(st_ + (uint32_t)(rr_ * ASTR + ac) * 2,                \
                       khb + (size_t)((n0_) + rr_) * (G_ * HD_) + ac);       \
        }                                                                    \
        _Pragma("unroll")                                                    \
        for (int it_ = 0; it_ < 2; it_++) {                                  \
            const int row_ = it_ * 32 + ar;                                  \
            const uint32_t so_ = (uint32_t)(row_ * ASTR + ac) * 2;           \
            CP_ASYNC16(st_ + KSTG + so_,                                     \
                       vhb + (size_t)row_ * T_ + (n0_) + ac);                \
            CP_ASYNC16(st_ + KSTG + VSUB + so_,                              \
                       vhb + (size_t)row_ * T_ + (n0_) + 64 + ac);           \
        }                                                                    \
        CP_COMMIT();                                                         \
    } while (0)

    AISSUE(0, 0);

    // ---- stage Q tile (128 rows, 256 threads) ----
    {
        const __half* qp = q16 + ((size_t)(b * T_ + m0) * H_ + h) * HD_;
        const uint32_t soff = (uint32_t)(ar * ASTR + ac) * 2;
#pragma unroll
        for (int it = 0; it < 4; it++) {
            uint4 a = *(const uint4*)(qp + (size_t)(it * 32 + ar) * (H_ * HD_) + ac);
            STS128(sQ + it * 32 * ASTR * 2 + soff, a);
        }
    }
    __syncthreads();

    uint32_t qf[4][4];
    {
        const uint32_t a_off = (uint32_t)((w * 16 + (lane & 15)) * ASTR * 2
                                          + (lane >> 4) * 16);
#pragma unroll
        for (int ks = 0; ks < 4; ks++)
            ldsm_x4(qf[ks], sQ + a_off + ks * 32);
    }

    float o[8][4];
#pragma unroll
    for (int nt = 0; nt < 8; nt++)
#pragma unroll
        for (int e = 0; e < 4; e++) o[nt][e] = 0.f;
    float lrow0 = 0.f, lrow1 = 0.f;

    const uint32_t b4_off = (uint32_t)((((lane & 7) + ((lane >> 4) & 1) * 8) * ASTR) * 2
                                       + ((lane >> 3) & 1) * 16);

    for (int t = 0; t < ntiles; t++) {
        CP_WAIT0();
        __syncthreads();
        if (t + 1 < ntiles) AISSUE((t + 1) * 128, (t + 1) & 1);

        const uint32_t kvb = sKV + (uint32_t)(t & 1) * KVSTG;

#pragma unroll
        for (int hh = 0; hh < 2; hh++) {
            const int n0 = t * 128 + hh * 64;
            const uint32_t sK = kvb + (uint32_t)hh * (64 * ASTR * 2);
            const uint32_t sV = kvb + KSTG + (uint32_t)hh * VSUB;

            if (n0 > m0 + w * 16 + 15) continue;   // fully masked for this warp
            const bool needm = (n0 + 63 > m0 + w * 16);

            // ---- S = Qs K^T ----
            float s[8][4];
#pragma unroll
            for (int nt = 0; nt < 8; nt++)
#pragma unroll
                for (int e = 0; e < 4; e++) s[nt][e] = 0.f;

#pragma unroll
            for (int ks = 0; ks < 4; ks++) {
#pragma unroll
                for (int ntp = 0; ntp < 4; ntp++) {
                    const uint32_t bo = b4_off + ntp * (16 * ASTR * 2) + ks * 32;
                    uint32_t bh[4];
                    ldsm_x4(bh, sK + bo);
                    mma_f16(s[2 * ntp],     qf[ks], bh[0], bh[1]);
                    mma_f16(s[2 * ntp + 1], qf[ks], bh[2], bh[3]);
                }
            }

            // ---- fixed-base softmax: p = 2^s, masked -> 0 ----
            uint32_t ap[4][4];
            {
                const int grow0 = m0 + w * 16 + (lane >> 2);
                const int grow1 = grow0 + 8;
                float s0 = 0.f, s1 = 0.f;
#pragma unroll
                for (int nt = 0; nt < 8; nt++) {
                    const int col = n0 + nt * 8 + (lane & 3) * 2;
                    float p0 = ex2(s[nt][0]);
                    float p1 = ex2(s[nt][1]);
                    float p2 = ex2(s[nt][2]);
                    float p3 = ex2(s[nt][3]);
                    if (needm) {
                        if (col     > grow0) p0 = 0.f;
                        if (col + 1 > grow0) p1 = 0.f;
                        if (col     > grow1) p2 = 0.f;
                        if (col + 1 > grow1) p3 = 0.f;
                    }
                    s0 += p0 + p1; s1 += p2 + p3;
                    s[nt][0] = p0; s[nt][1] = p1;
                    s[nt][2] = p2; s[nt][3] = p3;
                }
                lrow0 += s0;
                lrow1 += s1;
#pragma unroll
                for (int ks = 0; ks < 4; ks++) {
                    ap[ks][0] = pack_h2(s[2 * ks][0],     s[2 * ks][1]);
                    ap[ks][1] = pack_h2(s[2 * ks][2],     s[2 * ks][3]);
                    ap[ks][2] = pack_h2(s[2 * ks + 1][0], s[2 * ks + 1][1]);
                    ap[ks][3] = pack_h2(s[2 * ks + 1][2], s[2 * ks + 1][3]);
                }
            }

            // ---- O += P16 V16 ----
#pragma unroll
            for (int ntp = 0; ntp < 4; ntp++) {
#pragma unroll
                for (int ks = 0; ks < 4; ks++) {
                    const uint32_t bo = b4_off + ntp * (16 * ASTR * 2) + ks * 32;
                    uint32_t vh[4];
                    ldsm_x4(vh, sV + bo);
                    mma_f16(o[2 * ntp],     ap[ks], vh[0], vh[1]);
                    mma_f16(o[2 * ntp + 1], ap[ks], vh[2], vh[3]);
                }
            }
        }
    }
#undef AISSUE

    // ---- epilogue: quad-reduce l, normalize, emit fp16 ----
    {
        lrow0 += __shfl_xor_sync(0xffffffffu, lrow0, 1);
        lrow0 += __shfl_xor_sync(0xffffffffu, lrow0, 2);
        lrow1 += __shfl_xor_sync(0xffffffffu, lrow1, 1);
        lrow1 += __shfl_xor_sync(0xffffffffu, lrow1, 2);
        const float i0 = 1.f / lrow0;
        const float i1 = 1.f / lrow1;
        const int grow = m0 + w * 16 + (lane >> 2);
        const size_t base0 = (size_t)(b * T_ + grow) * D_ + h * HD_ + (lane & 3) * 2;
        const size_t base1 = base0 + 8 * D_;
#pragma unroll
        for (int nt = 0; nt < 8; nt++) {
            *(uint32_t*)&o16[base0 + nt * 8] =
                pack_h2(o[nt][0] * i0, o[nt][1] * i0);
            *(uint32_t*)&o16[base1 + nt * 8] =
                pack_h2(o[nt][2] * i1, o[nt][3] * i1);
        }
    }
}

// ---------------------------------------------------------------------------
// Launch
// ---------------------------------------------------------------------------
extern "C" void kernel_launch(void* const* d_in, const int* in_sizes, int n_in,
                              void* d_out, int out_size)
{
    const float* x    = (const float*)d_in[0];
    const float* Wq   = (const float*)d_in[1];
    const float* Wk   = (const float*)d_in[2];
    const float* Wv   = (const float*)d_in[3];
    const float* Wo   = (const float*)d_in[4];
    const float* qn_w = (const float*)d_in[5];
    const float* kn_w = (const float*)d_in[6];
    float* out = (float*)d_out;

    float2* cs;
    __half *qkv16, *x16, *wqkv16, *wo16, *q16, *k16, *vt16, *o16;
    cudaGetSymbolAddress((void**)&cs, g_cs);
    cudaGetSymbolAddress((void**)&qkv16, g_qkv16);
    cudaGetSymbolAddress((void**)&x16, g_x16);
    cudaGetSymbolAddress((void**)&wqkv16, g_wqkv16);
    cudaGetSymbolAddress((void**)&wo16, g_wo16);
    cudaGetSymbolAddress((void**)&q16, g_q16);
    cudaGetSymbolAddress((void**)&k16, g_k16);
    cudaGetSymbolAddress((void**)&vt16, g_vt16);
    cudaGetSymbolAddress((void**)&o16, g_o16);

    cudaFuncSetAttribute(gemm_h1<true>,
                         cudaFuncAttributeMaxDynamicSharedMemorySize, GEMM_SMEM);
    cudaFuncSetAttribute(gemm_h1<false>,
                         cudaFuncAttributeMaxDynamicSharedMemorySize, GEMM_SMEM);
    cudaFuncSetAttribute(attn_mma,
                         cudaFuncAttributeMaxDynamicSharedMemorySize, ATT_SMEM);

    // --- fused prologue ---
    prep<<<NB_TOT, 256>>>(x, Wq, Wk, Wv, Wo, x16, wqkv16, wo16, cs);

    // --- fused QKV projection (fp16 output) ---
    gemm_h1<true><<<dim3(QKVW / 128, BT_ / 128), 256, GEMM_SMEM>>>(
        x16, wqkv16, qkv16, BT_, QKVW, D_);

    // --- fused pointwise: RMSNorm+RoPE (q,k) + V transpose ---
    postproc<<<NB_RQ + NB_RK + NB_V, 256>>>(qkv16, qn_w, kn_w,
                                            q16, k16, vt16, cs);

    // --- causal GQA flash attention (128-key stages) ---
    attn_mma<<<dim3(T_ / 128, H_, B_), 256, ATT_SMEM>>>(q16, k16, vt16, o16);

    // --- output projection (fp32 output) ---
    gemm_h1<false><<<dim3(D_ / 128, BT_ / 128), 256, GEMM_SMEM>>>(
        o16, wo16, out, BT_, D_, D_);
}

// round 17
// speedup vs baseline: 1.0762x; 1.0166x over previous
#include <cuda_runtime.h>
#include <cuda_fp16.h>
#include <math.h>
#include <stdint.h>

// ---------------------------------------------------------------------------
// Problem constants
// ---------------------------------------------------------------------------
#define B_   4
#define T_   2048
#define D_   1024
#define H_   16
#define G_   4
#define HD_  64
#define BT_  (B_ * T_)          // 8192
#define QKVW 1536                // fused Q|K|V projection width
#define SC_LOG2E 0.18033688011112042f   // 0.125 * log2(e)

// ---------------------------------------------------------------------------
// Scratch (device globals -- no allocation allowed)
// ---------------------------------------------------------------------------
__device__ float2 g_cs[T_ * 32];

__device__ __half g_qkv16[BT_ * QKVW];    // fused q|k|v projection (fp16)
__device__ __half g_x16[BT_ * D_];
__device__ __half g_wqkv16[QKVW * D_];    // Wq | Wk | Wv rows
__device__ __half g_wo16[D_ * D_];
__device__ __half g_q16[BT_ * D_];        // pre-scaled by 0.125*log2e
__device__ __half g_k16[BT_ * G_ * HD_];
__device__ __half g_vt16[B_ * G_ * HD_ * T_];
__device__ __half g_o16[BT_ * D_];

// ---------------------------------------------------------------------------
// PTX helpers (base sm_100-legal)
// ---------------------------------------------------------------------------
__device__ __forceinline__ uint32_t smem_u32(const void* p) {
    uint32_t a;
    asm("{ .reg .u64 t; cvta.to.shared.u64 t, %1; cvt.u32.u64 %0, t; }"
        : "=r"(a) : "l"(p));
    return a;
}
__device__ __forceinline__ void ldsm_x4(uint32_t (&r)[4], uint32_t addr) {
    asm volatile("ldmatrix.sync.aligned.m8n8.x4.shared.b16 {%0,%1,%2,%3}, [%4];"
                 : "=r"(r[0]), "=r"(r[1]), "=r"(r[2]), "=r"(r[3]) : "r"(addr));
}
__device__ __forceinline__ void mma_f16(float (&d)[4], const uint32_t (&a)[4],
                                        uint32_t b0, uint32_t b1) {
    asm volatile(
        "mma.sync.aligned.m16n8k16.row.col.f32.f16.f16.f32 "
        "{%0,%1,%2,%3}, {%4,%5,%6,%7}, {%8,%9}, {%0,%1,%2,%3};"
        : "+f"(d[0]), "+f"(d[1]), "+f"(d[2]), "+f"(d[3])
        : "r"(a[0]), "r"(a[1]), "r"(a[2]), "r"(a[3]), "r"(b0), "r"(b1));
}
__device__ __forceinline__ uint32_t pack_h2(float x, float y) {
    __half2 h = __floats2half2_rn(x, y);
    return *(uint32_t*)&h;
}
__device__ __forceinline__ uint32_t ex2_h2(uint32_t x) {
    uint32_t y;
    asm("ex2.approx.f16x2 %0, %1;" : "=r"(y) : "r"(x));
    return y;
}
#define STS128(addr, v) \
    asm volatile("st.shared.v4.b32 [%0], {%1,%2,%3,%4};" \
                 :: "r"(addr), "r"((v).x), "r"((v).y), "r"((v).z), "r"((v).w))
#define CP_ASYNC16(dst, src) \
    asm volatile("cp.async.cg.shared.global [%0], [%1], 16;" \
                 :: "r"(dst), "l"(src))
#define CP_COMMIT() asm volatile("cp.async.commit_group;" ::: "memory")
#define CP_WAIT1()  asm volatile("cp.async.wait_group 1;" ::: "memory")
#define CP_WAIT0()  asm volatile("cp.async.wait_group 0;" ::: "memory")

// ---------------------------------------------------------------------------
// Fused prologue: x->fp16, Wq|Wk|Wv|Wo->fp16, rope table. One launch.
// ---------------------------------------------------------------------------
#define NB_X   8192
#define NB_WQ  1024
#define NB_WK  256
#define NB_WV  256
#define NB_WO  1024
#define NB_CS  256
#define NB_TOT (NB_X + NB_WQ + NB_WK + NB_WV + NB_WO + NB_CS)

__global__ void __launch_bounds__(256)
prep(const float* __restrict__ x,  const float* __restrict__ Wq,
     const float* __restrict__ Wk, const float* __restrict__ Wv,
     const float* __restrict__ Wo,
     __half* __restrict__ x16, __half* __restrict__ wqkv16,
     __half* __restrict__ wo16, float2* __restrict__ cs)
{
    const int bid = blockIdx.x;
    const int tid = threadIdx.x;

    const float* src; __half* dst; int i;
    if (bid < NB_X) {
        i = bid * 256 + tid; src = x; dst = x16;
    } else if (bid < NB_X + NB_WQ) {
        i = (bid - NB_X) * 256 + tid; src = Wq; dst = wqkv16;
    } else if (bid < NB_X + NB_WQ + NB_WK) {
        i = (bid - NB_X - NB_WQ) * 256 + tid;
        src = Wk; dst = wqkv16 + (size_t)D_ * D_;
    } else if (bid < NB_X + NB_WQ + NB_WK + NB_WV) {
        i = (bid - NB_X - NB_WQ - NB_WK) * 256 + tid;
        src = Wv; dst = wqkv16 + (size_t)(D_ + 256) * D_;
    } else if (bid < NB_X + NB_WQ + NB_WK + NB_WV + NB_WO) {
        i = (bid - NB_X - NB_WQ - NB_WK - NB_WV) * 256 + tid;
        src = Wo; dst = wo16;
    } else {
        const int idx = (bid - (NB_TOT - NB_CS)) * 256 + tid;
        const int t = idx >> 5, l = idx & 31;
        double inv_freq = pow(10000.0, -(double)l / 32.0);
        double ang = (double)t * inv_freq;
        cs[idx] = make_float2((float)cos(ang), (float)sin(ang));
        return;
    }
    float4 v = ((const float4*)src)[i];
    uint2 o = {pack_h2(v.x, v.y), pack_h2(v.z, v.w)};
    ((uint2*)dst)[i] = o;
}

// ---------------------------------------------------------------------------
// Tensor-core GEMM (HMMA fp16): C[M,N] = A16[M,K] @ B16[N,K]^T.
// CTA 128x128, 8 warps, warp tile 64x32, KC=32, 3-stage cp.async, 2 CTAs/SM.
// ---------------------------------------------------------------------------
#define KC      32
#define LDT     40
#define ATILEB  (128 * LDT * 2)
#define BTILEB  (128 * LDT * 2)
#define STAGEB  (ATILEB + BTILEB)
#define GEMM_SMEM (3 * STAGEB)            // 61440 B

template <bool HOUT>
__global__ void __launch_bounds__(256, 2)
gemm_h1(const __half* __restrict__ A16, const __half* __restrict__ B16,
        void* __restrict__ Cv, int M, int N, int K)
{
    extern __shared__ char smraw[];
    const uint32_t sb = smem_u32(smraw);

    const int tid  = threadIdx.x;
    const int lane = tid & 31;
    const int wid  = tid >> 5;
    const int wm   = wid & 1;
    const int wn   = wid >> 1;
    const int m0 = blockIdx.y * 128;
    const int n0 = blockIdx.x * 128;

    const int r0   = tid >> 2;
    const int cseg = (tid & 3) * 8;
    const __half* pA = A16 + (size_t)(m0 + r0) * K + cseg;
    const __half* pB = B16 + (size_t)(n0 + r0) * K + cseg;
    const uint32_t dA = (uint32_t)(r0 * LDT + cseg) * 2;
    const size_t rstep = (size_t)64 * K;
    const uint32_t dstep = 64 * LDT * 2;

    const uint32_t a_off = (uint32_t)(((wm * 64 + (lane & 15)) * LDT
                                       + (lane >> 4) * 8) * 2);
    const uint32_t b4_off = (uint32_t)(((wn * 32 + (lane & 7)
                                         + ((lane >> 4) & 1) * 8) * LDT) * 2
                                       + ((lane >> 3) & 1) * 16);

    float acc[4][4][4];
#pragma unroll
    for (int i = 0; i < 4; i++)
#pragma unroll
        for (int j = 0; j < 4; j++)
#pragma unroll
            for (int e = 0; e < 4; e++) acc[i][j][e] = 0.f;

    const int nch = K / KC;

#define ISSUE(c) do {                                                       \
        const uint32_t st_ = sb + ((c) % 3) * STAGEB;                       \
        const size_t k0_ = (size_t)(c) * KC;                                \
        CP_ASYNC16(st_ + dA,                    pA + k0_);                  \
        CP_ASYNC16(st_ + dA + dstep,            pA + k0_ + rstep);          \
        CP_ASYNC16(st_ + ATILEB + dA,           pB + k0_);                  \
        CP_ASYNC16(st_ + ATILEB + dA + dstep,   pB + k0_ + rstep);          \
        CP_COMMIT();                                                        \
    } while (0)

    ISSUE(0);
    ISSUE(1);

    for (int c = 0; c < nch; c++) {
        if (c + 2 < nch) CP_WAIT1(); else CP_WAIT0();
        __syncthreads();
        if (c + 2 < nch) ISSUE(c + 2);

        const uint32_t tb = sb + (c % 3) * STAGEB;
        const uint32_t aT = tb;
        const uint32_t bT = tb + ATILEB;

#pragma unroll
        for (int ks = 0; ks < 2; ks++) {
            const uint32_t ksb = ks * 32;
            uint32_t af[4][4];
#pragma unroll
            for (int mt = 0; mt < 4; mt++)
                ldsm_x4(af[mt], aT + a_off + mt * (16 * LDT * 2) + ksb);
#pragma unroll
            for (int ntp = 0; ntp < 2; ntp++) {
                uint32_t bh[4];
                ldsm_x4(bh, bT + b4_off + ntp * (16 * LDT * 2) + ksb);
#pragma unroll
                for (int mt = 0; mt < 4; mt++) {
                    mma_f16(acc[mt][2 * ntp],     af[mt], bh[0], bh[1]);
                    mma_f16(acc[mt][2 * ntp + 1], af[mt], bh[2], bh[3]);
                }
            }
        }
    }
#undef ISSUE

#pragma unroll
    for (int mt = 0; mt < 4; mt++) {
        const int r = m0 + wm * 64 + mt * 16 + (lane >> 2);
#pragma unroll
        for (int nt = 0; nt < 4; nt++) {
            const int cc = n0 + wn * 32 + nt * 8 + (lane & 3) * 2;
            if (HOUT) {
                __half* C = (__half*)Cv;
                *(uint32_t*)&C[(size_t)r * N + cc] =
                    pack_h2(acc[mt][nt][0], acc[mt][nt][1]);
                *(uint32_t*)&C[(size_t)(r + 8) * N + cc] =
                    pack_h2(acc[mt][nt][2], acc[mt][nt][3]);
            } else {
                float* C = (float*)Cv;
                float2 v0 = {acc[mt][nt][0], acc[mt][nt][1]};
                float2 v1 = {acc[mt][nt][2], acc[mt][nt][3]};
                *(float2*)&C[(size_t)r * N + cc]       = v0;
                *(float2*)&C[(size_t)(r + 8) * N + cc] = v1;
            }
        }
    }
}

// ---------------------------------------------------------------------------
// Fused pointwise: RMSNorm+RoPE for q (pre-scaled) and k, plus V transpose.
// ---------------------------------------------------------------------------
#define NB_RQ (BT_ * H_ / 8)   // 16384
#define NB_RK (BT_ * G_ / 8)   // 4096
#define NB_V  (T_ / 64 * G_ * B_)  // 512

__global__ void __launch_bounds__(256)
postproc(const __half* __restrict__ qkv,
         const float* __restrict__ qn_w, const float* __restrict__ kn_w,
         __half* __restrict__ q16, __half* __restrict__ k16,
         __half* __restrict__ vt16, const float2* __restrict__ cs)
{
    __shared__ __half sv[64][72];
    const int tid = threadIdx.x;

    if (blockIdx.x >= NB_RQ + NB_RK) {
        const int vb = blockIdx.x - NB_RQ - NB_RK;
        const int t0 = (vb & 31) * 64;
        const int g  = (vb >> 5) & 3;
        const int b  = vb >> 7;
        const __half* v = qkv + D_ + 256 + g * HD_;
#pragma unroll
        for (int it = 0; it < 2; it++) {
            int tr = it * 32 + (tid >> 3);
            int c8 = (tid & 7) * 8;
            uint4 raw = *(const uint4*)&v[(size_t)(b * T_ + t0 + tr) * QKVW + c8];
            *(uint4*)&sv[tr][c8] = raw;
        }
        __syncthreads();
        const int hd  = tid >> 2;
        const int seg = tid & 3;
        __half hv[16];
#pragma unroll
        for (int j = 0; j < 16; j++)
            hv[j] = sv[seg * 16 + j][hd];
        const size_t ob = ((size_t)(b * G_ + g) * HD_ + hd) * T_ + t0 + seg * 16;
        *(uint4*)&vt16[ob]     = *(uint4*)&hv[0];
        *(uint4*)&vt16[ob + 8] = *(uint4*)&hv[8];
        return;
    }

    const int lane   = tid & 31;
    const int warpid = tid >> 5;

    const __half* p;
    const float* w;
    __half* outp;
    int t;
    bool isq;
    if (blockIdx.x < NB_RQ) {
        const int row  = blockIdx.x * 8 + warpid;
        const int bt   = row >> 4;
        const int head = row & 15;
        t = bt & (T_ - 1);
        p = qkv + (size_t)bt * QKVW + head * HD_;
        w = qn_w;
        outp = q16 + (size_t)bt * D_ + head * HD_;
        isq = true;
    } else {
        const int row = (blockIdx.x - NB_RQ) * 8 + warpid;
        const int bt  = row >> 2;
        const int g   = row & 3;
        t = bt & (T_ - 1);
        p = qkv + (size_t)bt * QKVW + D_ + g * HD_;
        w = kn_w;
        outp = k16 + (size_t)bt * (G_ * HD_) + g * HD_;
        isq = false;
    }

    __half2 xh = *(const __half2*)&p[2 * lane];
    float x0 = __half2float(__low2half(xh));
    float x1 = __half2float(__high2half(xh));

    float ss = x0 * x0 + x1 * x1;
#pragma unroll
    for (int o = 16; o > 0; o >>= 1)
        ss += __shfl_xor_sync(0xffffffffu, ss, o);

    float rms = rsqrtf(ss * (1.0f / HD_) + 1e-6f);
    float xn1 = x0 * rms * w[2 * lane];
    float xn2 = x1 * rms * w[2 * lane + 1];

    float2 csv = cs[t * 32 + lane];
    float ox = xn1 * csv.x - xn2 * csv.y;
    float oy = xn2 * csv.x + xn1 * csv.y;
    if (isq) { ox *= SC_LOG2E; oy *= SC_LOG2E; }

    *(uint32_t*)&outp[2 * lane] = pack_h2(ox, oy);
}

// ---------------------------------------------------------------------------
// Causal GQA flash attention, HMMA fp16, fixed-base softmax in fp16x2.
// CTA = 128 q-rows, 8 warps x 16 rows (256 threads), 2 CTAs/SM.
// 128-key smem stages (double-buffered), two 64-key compute halves.
// Row sums computed by ones-MMA (no shuffles, no scalar adds).
// ---------------------------------------------------------------------------
#define ASTR  72
#define VSUB  (64 * ASTR * 2)            // 9216 B
#define KSTG  (128 * ASTR * 2)           // 18432 B
#define KVSTG (KSTG + 2 * VSUB)          // 36864 B per stage
#define AQT   (128 * ASTR * 2)           // 18432 B
#define ATT_SMEM (AQT + 2 * KVSTG)       // 92160 B
#define ONE_H2 0x3C003C00u               // fp16x2 {1.0, 1.0}

__global__ void __launch_bounds__(256, 2)
attn_mma(const __half* __restrict__ q16, const __half* __restrict__ k16,
         const __half* __restrict__ vt16, __half* __restrict__ o16)
{
    extern __shared__ char smraw[];
    const uint32_t sb  = smem_u32(smraw);
    const uint32_t sQ  = sb;
    const uint32_t sKV = sb + AQT;

    const int tid  = threadIdx.x;
    const int lane = tid & 31;
    const int w    = tid >> 5;            // 0..7, rows [w*16, w*16+16)
    const int mblk = gridDim.x - 1 - blockIdx.x;
    const int m0   = mblk * 128;
    const int h    = blockIdx.y;
    const int b    = blockIdx.z;
    const int g    = h >> 2;

    const __half* khb = k16 + ((size_t)b * T_ * G_ + g) * HD_;
    const __half* vhb = vt16 + (size_t)(b * G_ + g) * HD_ * T_;

    const int ntiles = mblk + 1;          // 128-key tiles

    const int ar = tid >> 3;             // 0..31
    const int ac = (tid & 7) * 8;
#define AISSUE(n0_, stg_) do {                                               \
        const uint32_t st_ = sKV + (uint32_t)(stg_) * KVSTG;                 \
        _Pragma("unroll")                                                    \
        for (int it_ = 0; it_ < 4; it_++) {                                  \
            const int rr_ = it_ * 32 + ar;                                   \
            CP_ASYNC16(st_ + (uint32_t)(rr_ * ASTR + ac) * 2,                \
                       khb + (size_t)((n0_) + rr_) * (G_ * HD_) + ac);       \
        }                                                                    \
        _Pragma("unroll")                                                    \
        for (int it_ = 0; it_ < 2; it_++) {                                  \
            const int row_ = it_ * 32 + ar;                                  \
            const uint32_t so_ = (uint32_t)(row_ * ASTR + ac) * 2;           \
            CP_ASYNC16(st_ + KSTG + so_,                                     \
                       vhb + (size_t)row_ * T_ + (n0_) + ac);                \
            CP_ASYNC16(st_ + KSTG + VSUB + so_,                              \
                       vhb + (size_t)row_ * T_ + (n0_) + 64 + ac);           \
        }                                                                    \
        CP_COMMIT();                                                         \
    } while (0)

    AISSUE(0, 0);

    // ---- stage Q tile (128 rows, 256 threads) ----
    {
        const __half* qp = q16 + ((size_t)(b * T_ + m0) * H_ + h) * HD_;
        const uint32_t soff = (uint32_t)(ar * ASTR + ac) * 2;
#pragma unroll
        for (int it = 0; it < 4; it++) {
            uint4 a = *(const uint4*)(qp + (size_t)(it * 32 + ar) * (H_ * HD_) + ac);
            STS128(sQ + it * 32 * ASTR * 2 + soff, a);
        }
    }
    __syncthreads();

    uint32_t qf[4][4];
    {
        const uint32_t a_off = (uint32_t)((w * 16 + (lane & 15)) * ASTR * 2
                                          + (lane >> 4) * 16);
#pragma unroll
        for (int ks = 0; ks < 4; ks++)
            ldsm_x4(qf[ks], sQ + a_off + ks * 32);
    }

    float o[8][4];
#pragma unroll
    for (int nt = 0; nt < 8; nt++)
#pragma unroll
        for (int e = 0; e < 4; e++) o[nt][e] = 0.f;
    float lacc[4] = {0.f, 0.f, 0.f, 0.f};   // row sums via ones-MMA

    const uint32_t b4_off = (uint32_t)((((lane & 7) + ((lane >> 4) & 1) * 8) * ASTR) * 2
                                       + ((lane >> 3) & 1) * 16);

    for (int t = 0; t < ntiles; t++) {
        CP_WAIT0();
        __syncthreads();
        if (t + 1 < ntiles) AISSUE((t + 1) * 128, (t + 1) & 1);

        const uint32_t kvb = sKV + (uint32_t)(t & 1) * KVSTG;

#pragma unroll
        for (int hh = 0; hh < 2; hh++) {
            const int n0 = t * 128 + hh * 64;
            const uint32_t sK = kvb + (uint32_t)hh * (64 * ASTR * 2);
            const uint32_t sV = kvb + KSTG + (uint32_t)hh * VSUB;

            if (n0 > m0 + w * 16 + 15) continue;   // fully masked for this warp
            const bool needm = (n0 + 63 > m0 + w * 16);

            // ---- S = Qs K^T ----
            float s[8][4];
#pragma unroll
            for (int nt = 0; nt < 8; nt++)
#pragma unroll
                for (int e = 0; e < 4; e++) s[nt][e] = 0.f;

#pragma unroll
            for (int ks = 0; ks < 4; ks++) {
#pragma unroll
                for (int ntp = 0; ntp < 4; ntp++) {
                    const uint32_t bo = b4_off + ntp * (16 * ASTR * 2) + ks * 32;
                    uint32_t bh[4];
                    ldsm_x4(bh, sK + bo);
                    mma_f16(s[2 * ntp],     qf[ks], bh[0], bh[1]);
                    mma_f16(s[2 * ntp + 1], qf[ks], bh[2], bh[3]);
                }
            }

            // ---- causal mask (diagonal tiles only): set s = -64 ----
            if (needm) {
                const int grow0 = m0 + w * 16 + (lane >> 2);
                const int grow1 = grow0 + 8;
#pragma unroll
                for (int nt = 0; nt < 8; nt++) {
                    const int col = n0 + nt * 8 + (lane & 3) * 2;
                    if (col     > grow0) s[nt][0] = -64.f;
                    if (col + 1 > grow0) s[nt][1] = -64.f;
                    if (col     > grow1) s[nt][2] = -64.f;
                    if (col + 1 > grow1) s[nt][3] = -64.f;
                }
            }

            // ---- p = 2^s in fp16x2; l via ones-MMA ----
            uint32_t ap[4][4];
#pragma unroll
            for (int ks = 0; ks < 4; ks++) {
                ap[ks][0] = ex2_h2(pack_h2(s[2 * ks][0],     s[2 * ks][1]));
                ap[ks][1] = ex2_h2(pack_h2(s[2 * ks][2],     s[2 * ks][3]));
                ap[ks][2] = ex2_h2(pack_h2(s[2 * ks + 1][0], s[2 * ks + 1][1]));
                ap[ks][3] = ex2_h2(pack_h2(s[2 * ks + 1][2], s[2 * ks + 1][3]));
            }
#pragma unroll
            for (int ks = 0; ks < 4; ks++)
                mma_f16(lacc, ap[ks], ONE_H2, ONE_H2);

            // ---- O += P16 V16 ----
#pragma unroll
            for (int ntp = 0; ntp < 4; ntp++) {
#pragma unroll
                for (int ks = 0; ks < 4; ks++) {
                    const uint32_t bo = b4_off + ntp * (16 * ASTR * 2) + ks * 32;
                    uint32_t vh[4];
                    ldsm_x4(vh, sV + bo);
                    mma_f16(o[2 * ntp],     ap[ks], vh[0], vh[1]);
                    mma_f16(o[2 * ntp + 1], ap[ks], vh[2], vh[3]);
                }
            }
        }
    }
#undef AISSUE

    // ---- epilogue: normalize (row sums already in lacc), emit fp16 ----
    {
        const float i0 = 1.f / lacc[0];
        const float i1 = 1.f / lacc[2];
        const int grow = m0 + w * 16 + (lane >> 2);
        const size_t base0 = (size_t)(b * T_ + grow) * D_ + h * HD_ + (lane & 3) * 2;
        const size_t base1 = base0 + 8 * D_;
#pragma unroll
        for (int nt = 0; nt < 8; nt++) {
            *(uint32_t*)&o16[base0 + nt * 8] =
                pack_h2(o[nt][0] * i0, o[nt][1] * i0);
            *(uint32_t*)&o16[base1 + nt * 8] =
                pack_h2(o[nt][2] * i1, o[nt][3] * i1);
        }
    }
}

// ---------------------------------------------------------------------------
// Launch
// ---------------------------------------------------------------------------
extern "C" void kernel_launch(void* const* d_in, const int* in_sizes, int n_in,
                              void* d_out, int out_size)
{
    const float* x    = (const float*)d_in[0];
    const float* Wq   = (const float*)d_in[1];
    const float* Wk   = (const float*)d_in[2];
    const float* Wv   = (const float*)d_in[3];
    const float* Wo   = (const float*)d_in[4];
    const float* qn_w = (const float*)d_in[5];
    const float* kn_w = (const float*)d_in[6];
    float* out = (float*)d_out;

    float2* cs;
    __half *qkv16, *x16, *wqkv16, *wo16, *q16, *k16, *vt16, *o16;
    cudaGetSymbolAddress((void**)&cs, g_cs);
    cudaGetSymbolAddress((void**)&qkv16, g_qkv16);
    cudaGetSymbolAddress((void**)&x16, g_x16);
    cudaGetSymbolAddress((void**)&wqkv16, g_wqkv16);
    cudaGetSymbolAddress((void**)&wo16, g_wo16);
    cudaGetSymbolAddress((void**)&q16, g_q16);
    cudaGetSymbolAddress((void**)&k16, g_k16);
    cudaGetSymbolAddress((void**)&vt16, g_vt16);
    cudaGetSymbolAddress((void**)&o16, g_o16);

    cudaFuncSetAttribute(gemm_h1<true>,
                         cudaFuncAttributeMaxDynamicSharedMemorySize, GEMM_SMEM);
    cudaFuncSetAttribute(gemm_h1<false>,
                         cudaFuncAttributeMaxDynamicSharedMemorySize, GEMM_SMEM);
    cudaFuncSetAttribute(attn_mma,
                         cudaFuncAttributeMaxDynamicSharedMemorySize, ATT_SMEM);

    // --- fused prologue ---
    prep<<<NB_TOT, 256>>>(x, Wq, Wk, Wv, Wo, x16, wqkv16, wo16, cs);

    // --- fused QKV projection (fp16 output) ---
    gemm_h1<true><<<dim3(QKVW / 128, BT_ / 128), 256, GEMM_SMEM>>>(
        x16, wqkv16, qkv16, BT_, QKVW, D_);

    // --- fused pointwise: RMSNorm+RoPE (q,k) + V transpose ---
    postproc<<<NB_RQ + NB_RK + NB_V, 256>>>(qkv16, qn_w, kn_w,
                                            q16, k16, vt16, cs);

    // --- causal GQA flash attention (fp16x2 softmax, ones-MMA row sums) ---
    attn_mma<<<dim3(T_ / 128, H_, B_), 256, ATT_SMEM>>>(q16, k16, vt16, o16);

    // --- output projection (fp32 output) ---
    gemm_h1<false><<<dim3(D_ / 128, BT_ / 128), 256, GEMM_SMEM>>>(
        o16, wo16, out, BT_, D_, D_);
}